// round 1
// baseline (speedup 1.0000x reference)
#include <cuda_runtime.h>
#include <cuda_bf16.h>
#include <math.h>

// ---------------------------------------------------------------------------
// MambaBottleneck: B=8, L=4096, D_MODEL=256, D_INNER=512, D_STATE=16,
// DT_RANK=16, D_CONV=4.  M = B*L = 32768 rows.
// Pipeline:
//   1. xz(M,1024) = x(M,256) @ in_proj_w^T             [SGEMM]
//   2. conv4+SiLU on u=xz[:, :512] -> uc(M,512), uct(CH,L)  (CH = b*512+d)
//   3. xdbl(M,48) = uc @ x_proj_w^T                    [SGEMM]
//   4. delta_t(CH,L) = softplus(xdbl[:, :16] @ dt_w^T + b)  (transposed write)
//   5. selective scan per channel (half-warp = 16 states) -> yscan_t(CH,L)
//   6. y(M,512) = (yscan^T + D*uc) * silu(z)           (tiled transpose)
//   7. outtmp(M,256) = y @ out_proj_w^T                [SGEMM]
//   8. out = LayerNorm(outtmp + x) * g + b
// ---------------------------------------------------------------------------

#define BATCH   8
#define SEQLEN  4096
#define DMODEL  256
#define DINNER  512
#define DSTATE  16
#define MROWS   (BATCH * SEQLEN)          // 32768
#define NCH     (BATCH * DINNER)          // 4096

// scratch layout (floats)
#define OFF_XZ      0
#define SZ_XZ       (MROWS * 1024)            // 33,554,432
#define OFF_UC      (OFF_XZ + SZ_XZ)
#define SZ_UC       (MROWS * DINNER)          // 16,777,216
#define OFF_UCT     (OFF_UC + SZ_UC)
#define SZ_UCT      (NCH * SEQLEN)            // 16,777,216
#define OFF_XDBL    (OFF_UCT + SZ_UCT)
#define SZ_XDBL     (MROWS * 48)              // 1,572,864
#define OFF_DELTAT  (OFF_XDBL + SZ_XDBL)
#define SZ_DELTAT   (NCH * SEQLEN)
#define OFF_YSCANT  (OFF_DELTAT + SZ_DELTAT)
#define SZ_YSCANT   (NCH * SEQLEN)
#define OFF_Y       (OFF_YSCANT + SZ_YSCANT)
#define SZ_Y        (MROWS * DINNER)
#define OFF_OUTTMP  (OFF_Y + SZ_Y)
#define SZ_OUTTMP   (MROWS * DMODEL)          // 8,388,608
#define SCRATCH_TOTAL (OFF_OUTTMP + SZ_OUTTMP)

static __device__ float g_scratch[SCRATCH_TOTAL];

// ---------------------------------------------------------------------------
// Generic SGEMM: C[M,N] = A[M,K] @ W[N,K]^T   (A, W, C row-major)
// Tile 128x64x16, 256 threads, 8x4 per thread. K % 16 == 0, M % 128 == 0.
// N may be non-multiple of 64 (guarded).
// ---------------------------------------------------------------------------
__global__ __launch_bounds__(256) void sgemm_kernel(
    const float* __restrict__ A, const float* __restrict__ W,
    float* __restrict__ C, int M, int N, int K)
{
    __shared__ float As[16 * 128];
    __shared__ float Bs[16 * 64];

    const int bm = blockIdx.y * 128;
    const int bn = blockIdx.x * 64;
    const int tid = threadIdx.x;
    const int tx = tid & 15;        // 0..15 -> 4 cols each
    const int ty = tid >> 4;        // 0..15 -> 8 rows each

    float acc[8][4];
#pragma unroll
    for (int i = 0; i < 8; i++)
#pragma unroll
        for (int j = 0; j < 4; j++) acc[i][j] = 0.f;

    const int ar = tid >> 1, ak = (tid & 1) * 8;   // A tile load: row, k-offset
    const int br = tid >> 2, bk = (tid & 3) * 4;   // W tile load
    const bool bval = (bn + br) < N;

    const float* Ap = A + (size_t)(bm + ar) * K + ak;
    const float* Wp = W + (size_t)(bval ? (bn + br) : 0) * K + bk;

    for (int k0 = 0; k0 < K; k0 += 16) {
        float4 a0 = *(const float4*)(Ap + k0);
        float4 a1 = *(const float4*)(Ap + k0 + 4);
        float4 bv = *(const float4*)(Wp + k0);
        if (!bval) { bv.x = bv.y = bv.z = bv.w = 0.f; }

        As[(ak + 0) * 128 + ar] = a0.x;
        As[(ak + 1) * 128 + ar] = a0.y;
        As[(ak + 2) * 128 + ar] = a0.z;
        As[(ak + 3) * 128 + ar] = a0.w;
        As[(ak + 4) * 128 + ar] = a1.x;
        As[(ak + 5) * 128 + ar] = a1.y;
        As[(ak + 6) * 128 + ar] = a1.z;
        As[(ak + 7) * 128 + ar] = a1.w;
        Bs[(bk + 0) * 64 + br] = bv.x;
        Bs[(bk + 1) * 64 + br] = bv.y;
        Bs[(bk + 2) * 64 + br] = bv.z;
        Bs[(bk + 3) * 64 + br] = bv.w;
        __syncthreads();

#pragma unroll
        for (int kk = 0; kk < 16; kk++) {
            float4 av0 = *(const float4*)&As[kk * 128 + ty * 8];
            float4 av1 = *(const float4*)&As[kk * 128 + ty * 8 + 4];
            float4 bv4 = *(const float4*)&Bs[kk * 64 + tx * 4];
            float a[8] = {av0.x, av0.y, av0.z, av0.w, av1.x, av1.y, av1.z, av1.w};
            float b[4] = {bv4.x, bv4.y, bv4.z, bv4.w};
#pragma unroll
            for (int i = 0; i < 8; i++)
#pragma unroll
                for (int j = 0; j < 4; j++)
                    acc[i][j] = fmaf(a[i], b[j], acc[i][j]);
        }
        __syncthreads();
    }

#pragma unroll
    for (int i = 0; i < 8; i++) {
        const int row = bm + ty * 8 + i;
#pragma unroll
        for (int j = 0; j < 4; j++) {
            const int col = bn + tx * 4 + j;
            if (col < N) C[(size_t)row * N + col] = acc[i][j];
        }
    }
}

// ---------------------------------------------------------------------------
// Depthwise causal conv4 + SiLU. Reads u = xz[:, 0:512].
// Writes uc (M,512) and uct (CH,L) transposed.
// Grid: (512/32 dtiles, 4096/32 ltiles, 8 batches), 256 threads.
// ---------------------------------------------------------------------------
__global__ __launch_bounds__(256) void conv_silu_kernel(
    const float* __restrict__ xz, const float* __restrict__ cw,
    const float* __restrict__ cb, float* __restrict__ uc,
    float* __restrict__ uct)
{
    __shared__ float su[35][33];
    __shared__ float so[32][33];
    const int d0 = blockIdx.x * 32;
    const int l0 = blockIdx.y * 32;
    const int b  = blockIdx.z;
    const int tx = threadIdx.x & 31;
    const int ty = threadIdx.x >> 5;   // 0..7

    for (int r = ty; r < 35; r += 8) {
        const int l = l0 - 3 + r;
        float v = 0.f;
        if (l >= 0) v = xz[(size_t)(b * SEQLEN + l) * 1024 + d0 + tx];
        su[r][tx] = v;
    }
    __syncthreads();

    const int d = d0 + tx;
    const float w0 = cw[d * 4 + 0], w1 = cw[d * 4 + 1];
    const float w2 = cw[d * 4 + 2], w3 = cw[d * 4 + 3];
    const float bb = cb[d];

    for (int ll = ty; ll < 32; ll += 8) {
        float acc = su[ll][tx] * w0 + su[ll + 1][tx] * w1
                  + su[ll + 2][tx] * w2 + su[ll + 3][tx] * w3 + bb;
        const float sv = acc / (1.f + __expf(-acc));     // SiLU
        const int m = b * SEQLEN + l0 + ll;
        uc[(size_t)m * DINNER + d] = sv;
        so[ll][tx] = sv;
    }
    __syncthreads();

    for (int dd = ty; dd < 32; dd += 8)
        uct[(size_t)(b * DINNER + d0 + dd) * SEQLEN + l0 + tx] = so[tx][dd];
}

// ---------------------------------------------------------------------------
// delta_t(CH,L) = softplus(xdbl[:, 0:16] @ dt_proj_w^T + dt_proj_b)
// Grid: (512/32 dtiles, 32768/32 mtiles), 256 threads. m-tiles never cross b.
// ---------------------------------------------------------------------------
__global__ __launch_bounds__(256) void dtproj_kernel(
    const float* __restrict__ xdbl, const float* __restrict__ dtw,
    const float* __restrict__ dtb, float* __restrict__ deltat)
{
    __shared__ float sdt[32][17];
    __shared__ float sw[32][17];
    __shared__ float so[32][33];
    const int d0 = blockIdx.x * 32;
    const int m0 = blockIdx.y * 32;
    const int tid = threadIdx.x;

    {
        const int r = tid >> 4, c = tid & 15;
        sdt[r][c]      = xdbl[(size_t)(m0 + r) * 48 + c];
        sdt[r + 16][c] = xdbl[(size_t)(m0 + r + 16) * 48 + c];
        sw[r][c]       = dtw[(d0 + r) * 16 + c];
        sw[r + 16][c]  = dtw[(d0 + r + 16) * 16 + c];
    }
    __syncthreads();

    const int dloc = tid & 31;
    const float bias = dtb[d0 + dloc];
    for (int ll = tid >> 5; ll < 32; ll += 8) {
        float acc = bias;
#pragma unroll
        for (int k = 0; k < 16; k++) acc = fmaf(sdt[ll][k], sw[dloc][k], acc);
        so[ll][dloc] = (acc > 20.f) ? acc : log1pf(__expf(acc));  // softplus
    }
    __syncthreads();

    const int b  = m0 / SEQLEN;
    const int l0 = m0 % SEQLEN;
    for (int dd = tid >> 5; dd < 32; dd += 8)
        deltat[(size_t)(b * DINNER + d0 + dd) * SEQLEN + l0 + dloc] = so[dloc][dd];
}

// ---------------------------------------------------------------------------
// Selective scan. Half-warp (16 lanes) per channel, lane = state index s.
//   dA = exp(delta * A[d,s]);  state = state*dA + delta*u*B[s];  y = sum_s state*C[s]
// B = xdbl[m, 16+s], C = xdbl[m, 32+s].
// 4096 channels -> 2048 warps -> 256 blocks of 256 threads.
// ---------------------------------------------------------------------------
__global__ __launch_bounds__(256) void scan_kernel(
    const float* __restrict__ deltat, const float* __restrict__ uct,
    const float* __restrict__ xdbl, const float* __restrict__ Alog,
    float* __restrict__ yscant)
{
    const int warp = (blockIdx.x * blockDim.x + threadIdx.x) >> 5;
    const int lane = threadIdx.x & 31;
    const int half = lane >> 4;
    const int s    = lane & 15;
    const int ch   = warp * 2 + half;      // 0..4095
    const int b    = ch >> 9;
    const int d    = ch & 511;

    const float A = -__expf(Alog[d * DSTATE + s]);
    float state = 0.f;

    const float* dptr = deltat + (size_t)ch * SEQLEN;
    const float* uptr = uct    + (size_t)ch * SEQLEN;
    const float* xrow = xdbl   + (size_t)b * SEQLEN * 48;
    float* yout = yscant + (size_t)ch * SEQLEN;

    for (int l = 0; l < SEQLEN; l++) {
        const float dt = __ldg(dptr + l);
        const float ut = __ldg(uptr + l);
        const float Bv = __ldg(xrow + l * 48 + 16 + s);
        const float Cv = __ldg(xrow + l * 48 + 32 + s);
        const float dA = __expf(dt * A);
        state = fmaf(state, dA, dt * ut * Bv);
        float p = state * Cv;
        p += __shfl_xor_sync(0xffffffffu, p, 8);
        p += __shfl_xor_sync(0xffffffffu, p, 4);
        p += __shfl_xor_sync(0xffffffffu, p, 2);
        p += __shfl_xor_sync(0xffffffffu, p, 1);
        if (s == 0) yout[l] = p;
    }
}

// ---------------------------------------------------------------------------
// Gate: y(M,512) = (yscan^T + D*uc) * silu(z), z = xz[:, 512:1024].
// Tiled transpose read of yscan_t. Grid (16,128,8), 256 threads.
// ---------------------------------------------------------------------------
__global__ __launch_bounds__(256) void gate_kernel(
    const float* __restrict__ yscant, const float* __restrict__ uc,
    const float* __restrict__ xz, const float* __restrict__ Dw,
    float* __restrict__ y)
{
    __shared__ float s[32][33];
    const int d0 = blockIdx.x * 32;
    const int l0 = blockIdx.y * 32;
    const int b  = blockIdx.z;
    const int tx = threadIdx.x & 31;
    const int ty = threadIdx.x >> 5;

    for (int dd = ty; dd < 32; dd += 8)
        s[dd][tx] = yscant[(size_t)(b * DINNER + d0 + dd) * SEQLEN + l0 + tx];
    __syncthreads();

    const int d = d0 + tx;
    const float Dv = Dw[d];
    for (int ll = ty; ll < 32; ll += 8) {
        const int m = b * SEQLEN + l0 + ll;
        const float ucv = uc[(size_t)m * DINNER + d];
        const float zv  = xz[(size_t)m * 1024 + DINNER + d];
        const float silu_z = zv / (1.f + __expf(-zv));
        y[(size_t)m * DINNER + d] = (s[tx][ll] + Dv * ucv) * silu_z;
    }
}

// ---------------------------------------------------------------------------
// Residual + LayerNorm. Warp per row (256 cols, 8 per lane). Grid M/8, 256 thr.
// ---------------------------------------------------------------------------
__global__ __launch_bounds__(256) void ln_kernel(
    const float* __restrict__ outtmp, const float* __restrict__ x,
    const float* __restrict__ g, const float* __restrict__ beta,
    float* __restrict__ out)
{
    const int warp = threadIdx.x >> 5;
    const int lane = threadIdx.x & 31;
    const int row = blockIdx.x * 8 + warp;

    float h[8];
    float sum = 0.f, sq = 0.f;
#pragma unroll
    for (int i = 0; i < 8; i++) {
        const int c = lane + i * 32;
        const float v = outtmp[(size_t)row * 256 + c] + x[(size_t)row * 256 + c];
        h[i] = v; sum += v; sq = fmaf(v, v, sq);
    }
#pragma unroll
    for (int o = 16; o; o >>= 1) {
        sum += __shfl_xor_sync(0xffffffffu, sum, o);
        sq  += __shfl_xor_sync(0xffffffffu, sq,  o);
    }
    const float mu  = sum * (1.f / 256.f);
    const float var = sq * (1.f / 256.f) - mu * mu;
    const float inv = rsqrtf(var + 1e-5f);
#pragma unroll
    for (int i = 0; i < 8; i++) {
        const int c = lane + i * 32;
        out[(size_t)row * 256 + c] = (h[i] - mu) * inv * g[c] + beta[c];
    }
}

// ---------------------------------------------------------------------------
extern "C" void kernel_launch(void* const* d_in, const int* in_sizes, int n_in,
                              void* d_out, int out_size)
{
    const float* x       = (const float*)d_in[0];   // (8,4096,256)
    const float* in_w    = (const float*)d_in[1];   // (1024,256)
    const float* conv_w  = (const float*)d_in[2];   // (512,1,4)
    const float* conv_b  = (const float*)d_in[3];   // (512)
    const float* xproj_w = (const float*)d_in[4];   // (48,512)
    const float* dt_w    = (const float*)d_in[5];   // (512,16)
    const float* dt_b    = (const float*)d_in[6];   // (512)
    const float* A_log   = (const float*)d_in[7];   // (512,16)
    const float* Dw      = (const float*)d_in[8];   // (512)
    const float* out_w   = (const float*)d_in[9];   // (256,512)
    const float* ln_g    = (const float*)d_in[10];  // (256)
    const float* ln_b    = (const float*)d_in[11];  // (256)
    float* out = (float*)d_out;

    float* base = nullptr;
    cudaGetSymbolAddress((void**)&base, g_scratch);
    float* xz     = base + OFF_XZ;
    float* uc     = base + OFF_UC;
    float* uct    = base + OFF_UCT;
    float* xdbl   = base + OFF_XDBL;
    float* deltat = base + OFF_DELTAT;
    float* yscant = base + OFF_YSCANT;
    float* y      = base + OFF_Y;
    float* outtmp = base + OFF_OUTTMP;

    // 1. in_proj: xz = x @ in_w^T   (M=32768, N=1024, K=256)
    sgemm_kernel<<<dim3(1024 / 64, MROWS / 128), 256>>>(x, in_w, xz, MROWS, 1024, 256);

    // 2. conv4 + SiLU (+ transpose)
    conv_silu_kernel<<<dim3(DINNER / 32, SEQLEN / 32, BATCH), 256>>>(xz, conv_w, conv_b, uc, uct);

    // 3. x_proj: xdbl = uc @ xproj_w^T   (N=48, K=512)
    sgemm_kernel<<<dim3(1, MROWS / 128), 256>>>(uc, xproj_w, xdbl, MROWS, 48, 512);

    // 4. dt_proj + softplus (transposed write)
    dtproj_kernel<<<dim3(DINNER / 32, MROWS / 32), 256>>>(xdbl, dt_w, dt_b, deltat);

    // 5. selective scan
    scan_kernel<<<NCH / 8, 256>>>(deltat, uct, xdbl, A_log, yscant);

    // 6. gate + skip
    gate_kernel<<<dim3(DINNER / 32, SEQLEN / 32, BATCH), 256>>>(yscant, uc, xz, Dw, y);

    // 7. out_proj: outtmp = y @ out_w^T   (N=256, K=512)
    sgemm_kernel<<<dim3(256 / 64, MROWS / 128), 256>>>(y, out_w, outtmp, MROWS, 256, 512);

    // 8. residual + LayerNorm
    ln_kernel<<<MROWS / 8, 256>>>(outtmp, x, ln_g, ln_b, out);
}

// round 4
// speedup vs baseline: 1.2529x; 1.2529x over previous
#include <cuda_runtime.h>
#include <cuda_bf16.h>
#include <math.h>

// ---------------------------------------------------------------------------
// MambaBottleneck: B=8, L=4096, D_MODEL=256, D_INNER=512, D_STATE=16,
// DT_RANK=16, D_CONV=4.  M = B*L = 32768 rows.
// ---------------------------------------------------------------------------

#define BATCH   8
#define SEQLEN  4096
#define DMODEL  256
#define DINNER  512
#define DSTATE  16
#define MROWS   (BATCH * SEQLEN)          // 32768
#define NCH     (BATCH * DINNER)          // 4096

// scratch layout (floats)
#define OFF_XZ      0
#define SZ_XZ       (MROWS * 1024)
#define OFF_UC      (OFF_XZ + SZ_XZ)
#define SZ_UC       (MROWS * DINNER)
#define OFF_UCT     (OFF_UC + SZ_UC)
#define SZ_UCT      (NCH * SEQLEN)
#define OFF_XDBL    (OFF_UCT + SZ_UCT)
#define SZ_XDBL     (MROWS * 48)
#define OFF_DELTAT  (OFF_XDBL + SZ_XDBL)
#define SZ_DELTAT   (NCH * SEQLEN)
#define OFF_YSCANT  (OFF_DELTAT + SZ_DELTAT)
#define SZ_YSCANT   (NCH * SEQLEN)
#define OFF_Y       (OFF_YSCANT + SZ_YSCANT)
#define SZ_Y        (MROWS * DINNER)
#define OFF_OUTTMP  (OFF_Y + SZ_Y)
#define SZ_OUTTMP   (MROWS * DMODEL)
#define SCRATCH_TOTAL (OFF_OUTTMP + SZ_OUTTMP)

static __device__ float g_scratch[SCRATCH_TOTAL];

// ---------------------------------------------------------------------------
// SGEMM 128x128x8, double-buffered. C[M,N] = A[M,K] @ W[N,K]^T.
// 256 threads, 8x8 per thread. Requires M%128==0, N%128==0, K%8==0.
// ---------------------------------------------------------------------------
__global__ __launch_bounds__(256) void sgemm128_kernel(
    const float* __restrict__ A, const float* __restrict__ W,
    float* __restrict__ C, int M, int N, int K)
{
    __shared__ float As[2][8][128];
    __shared__ float Bs[2][8][128];

    const int bm = blockIdx.y * 128;
    const int bn = blockIdx.x * 128;
    const int tid = threadIdx.x;
    const int tx = tid & 15;       // n-group
    const int ty = tid >> 4;       // m-group

    const int lr = tid >> 1;            // row within tile (0..127)
    const int lk = (tid & 1) * 4;       // k offset (0 or 4)
    const float* Ap = A + (size_t)(bm + lr) * K + lk;
    const float* Wp = W + (size_t)(bn + lr) * K + lk;

    float acc[8][8];
#pragma unroll
    for (int i = 0; i < 8; i++)
#pragma unroll
        for (int j = 0; j < 8; j++) acc[i][j] = 0.f;

    const int KT = K >> 3;

    float4 ra = *(const float4*)(Ap);
    float4 rw = *(const float4*)(Wp);
    As[0][lk + 0][lr] = ra.x; As[0][lk + 1][lr] = ra.y;
    As[0][lk + 2][lr] = ra.z; As[0][lk + 3][lr] = ra.w;
    Bs[0][lk + 0][lr] = rw.x; Bs[0][lk + 1][lr] = rw.y;
    Bs[0][lk + 2][lr] = rw.z; Bs[0][lk + 3][lr] = rw.w;
    __syncthreads();

    for (int kt = 0; kt < KT; kt++) {
        const int cur = kt & 1;
        const int nxt = cur ^ 1;
        if (kt + 1 < KT) {
            ra = *(const float4*)(Ap + (size_t)(kt + 1) * 8);
            rw = *(const float4*)(Wp + (size_t)(kt + 1) * 8);
        }
#pragma unroll
        for (int kk = 0; kk < 8; kk++) {
            float4 a0 = *(const float4*)&As[cur][kk][ty * 4];
            float4 a1 = *(const float4*)&As[cur][kk][64 + ty * 4];
            float4 b0 = *(const float4*)&Bs[cur][kk][tx * 4];
            float4 b1 = *(const float4*)&Bs[cur][kk][64 + tx * 4];
            float a[8] = {a0.x, a0.y, a0.z, a0.w, a1.x, a1.y, a1.z, a1.w};
            float b[8] = {b0.x, b0.y, b0.z, b0.w, b1.x, b1.y, b1.z, b1.w};
#pragma unroll
            for (int i = 0; i < 8; i++)
#pragma unroll
                for (int j = 0; j < 8; j++)
                    acc[i][j] = fmaf(a[i], b[j], acc[i][j]);
        }
        if (kt + 1 < KT) {
            As[nxt][lk + 0][lr] = ra.x; As[nxt][lk + 1][lr] = ra.y;
            As[nxt][lk + 2][lr] = ra.z; As[nxt][lk + 3][lr] = ra.w;
            Bs[nxt][lk + 0][lr] = rw.x; Bs[nxt][lk + 1][lr] = rw.y;
            Bs[nxt][lk + 2][lr] = rw.z; Bs[nxt][lk + 3][lr] = rw.w;
            __syncthreads();
        }
    }

#pragma unroll
    for (int i = 0; i < 8; i++) {
        const int row = bm + ((i < 4) ? (ty * 4 + i) : (64 + ty * 4 + i - 4));
        float4 v0 = make_float4(acc[i][0], acc[i][1], acc[i][2], acc[i][3]);
        float4 v1 = make_float4(acc[i][4], acc[i][5], acc[i][6], acc[i][7]);
        *(float4*)(C + (size_t)row * N + bn + tx * 4)      = v0;
        *(float4*)(C + (size_t)row * N + bn + 64 + tx * 4) = v1;
    }
}

// ---------------------------------------------------------------------------
// SGEMM 128x64x16 (for x_proj, N=48 with guard).
// ---------------------------------------------------------------------------
__global__ __launch_bounds__(256) void sgemm_kernel(
    const float* __restrict__ A, const float* __restrict__ W,
    float* __restrict__ C, int M, int N, int K)
{
    __shared__ float As[16 * 128];
    __shared__ float Bs[16 * 64];

    const int bm = blockIdx.y * 128;
    const int bn = blockIdx.x * 64;
    const int tid = threadIdx.x;
    const int tx = tid & 15;
    const int ty = tid >> 4;

    float acc[8][4];
#pragma unroll
    for (int i = 0; i < 8; i++)
#pragma unroll
        for (int j = 0; j < 4; j++) acc[i][j] = 0.f;

    const int ar = tid >> 1, ak = (tid & 1) * 8;
    const int br = tid >> 2, bk = (tid & 3) * 4;
    const bool bval = (bn + br) < N;

    const float* Ap = A + (size_t)(bm + ar) * K + ak;
    const float* Wp = W + (size_t)(bval ? (bn + br) : 0) * K + bk;

    for (int k0 = 0; k0 < K; k0 += 16) {
        float4 a0 = *(const float4*)(Ap + k0);
        float4 a1 = *(const float4*)(Ap + k0 + 4);
        float4 bv = *(const float4*)(Wp + k0);
        if (!bval) { bv.x = bv.y = bv.z = bv.w = 0.f; }

        As[(ak + 0) * 128 + ar] = a0.x;
        As[(ak + 1) * 128 + ar] = a0.y;
        As[(ak + 2) * 128 + ar] = a0.z;
        As[(ak + 3) * 128 + ar] = a0.w;
        As[(ak + 4) * 128 + ar] = a1.x;
        As[(ak + 5) * 128 + ar] = a1.y;
        As[(ak + 6) * 128 + ar] = a1.z;
        As[(ak + 7) * 128 + ar] = a1.w;
        Bs[(bk + 0) * 64 + br] = bv.x;
        Bs[(bk + 1) * 64 + br] = bv.y;
        Bs[(bk + 2) * 64 + br] = bv.z;
        Bs[(bk + 3) * 64 + br] = bv.w;
        __syncthreads();

#pragma unroll
        for (int kk = 0; kk < 16; kk++) {
            float4 av0 = *(const float4*)&As[kk * 128 + ty * 8];
            float4 av1 = *(const float4*)&As[kk * 128 + ty * 8 + 4];
            float4 bv4 = *(const float4*)&Bs[kk * 64 + tx * 4];
            float a[8] = {av0.x, av0.y, av0.z, av0.w, av1.x, av1.y, av1.z, av1.w};
            float b[4] = {bv4.x, bv4.y, bv4.z, bv4.w};
#pragma unroll
            for (int i = 0; i < 8; i++)
#pragma unroll
                for (int j = 0; j < 4; j++)
                    acc[i][j] = fmaf(a[i], b[j], acc[i][j]);
        }
        __syncthreads();
    }

#pragma unroll
    for (int i = 0; i < 8; i++) {
        const int row = bm + ty * 8 + i;
#pragma unroll
        for (int j = 0; j < 4; j++) {
            const int col = bn + tx * 4 + j;
            if (col < N) C[(size_t)row * N + col] = acc[i][j];
        }
    }
}

// ---------------------------------------------------------------------------
// Depthwise causal conv4 + SiLU. Writes uc (M,512) and uct (CH,L).
// ---------------------------------------------------------------------------
__global__ __launch_bounds__(256) void conv_silu_kernel(
    const float* __restrict__ xz, const float* __restrict__ cw,
    const float* __restrict__ cb, float* __restrict__ uc,
    float* __restrict__ uct)
{
    __shared__ float su[35][33];
    __shared__ float so[32][33];
    const int d0 = blockIdx.x * 32;
    const int l0 = blockIdx.y * 32;
    const int b  = blockIdx.z;
    const int tx = threadIdx.x & 31;
    const int ty = threadIdx.x >> 5;

    for (int r = ty; r < 35; r += 8) {
        const int l = l0 - 3 + r;
        float v = 0.f;
        if (l >= 0) v = xz[(size_t)(b * SEQLEN + l) * 1024 + d0 + tx];
        su[r][tx] = v;
    }
    __syncthreads();

    const int d = d0 + tx;
    const float w0 = cw[d * 4 + 0], w1 = cw[d * 4 + 1];
    const float w2 = cw[d * 4 + 2], w3 = cw[d * 4 + 3];
    const float bb = cb[d];

    for (int ll = ty; ll < 32; ll += 8) {
        float acc = su[ll][tx] * w0 + su[ll + 1][tx] * w1
                  + su[ll + 2][tx] * w2 + su[ll + 3][tx] * w3 + bb;
        const float sv = acc / (1.f + __expf(-acc));
        const int m = b * SEQLEN + l0 + ll;
        uc[(size_t)m * DINNER + d] = sv;
        so[ll][tx] = sv;
    }
    __syncthreads();

    for (int dd = ty; dd < 32; dd += 8)
        uct[(size_t)(b * DINNER + d0 + dd) * SEQLEN + l0 + tx] = so[tx][dd];
}

// ---------------------------------------------------------------------------
// delta_t(CH,L) = softplus(xdbl[:, 0:16] @ dt_proj_w^T + dt_proj_b)
// ---------------------------------------------------------------------------
__global__ __launch_bounds__(256) void dtproj_kernel(
    const float* __restrict__ xdbl, const float* __restrict__ dtw,
    const float* __restrict__ dtb, float* __restrict__ deltat)
{
    __shared__ float sdt[32][17];
    __shared__ float sw[32][17];
    __shared__ float so[32][33];
    const int d0 = blockIdx.x * 32;
    const int m0 = blockIdx.y * 32;
    const int tid = threadIdx.x;

    {
        const int r = tid >> 4, c = tid & 15;
        sdt[r][c]      = xdbl[(size_t)(m0 + r) * 48 + c];
        sdt[r + 16][c] = xdbl[(size_t)(m0 + r + 16) * 48 + c];
        sw[r][c]       = dtw[(d0 + r) * 16 + c];
        sw[r + 16][c]  = dtw[(d0 + r + 16) * 16 + c];
    }
    __syncthreads();

    const int dloc = tid & 31;
    const float bias = dtb[d0 + dloc];
    for (int ll = tid >> 5; ll < 32; ll += 8) {
        float acc = bias;
#pragma unroll
        for (int k = 0; k < 16; k++) acc = fmaf(sdt[ll][k], sw[dloc][k], acc);
        // fast stable softplus: max(x,0) + log(1 + exp(-|x|))
        so[ll][dloc] = fmaxf(acc, 0.f) + __logf(1.f + __expf(-fabsf(acc)));
    }
    __syncthreads();

    const int b  = m0 / SEQLEN;
    const int l0 = m0 % SEQLEN;
    for (int dd = tid >> 5; dd < 32; dd += 8)
        deltat[(size_t)(b * DINNER + d0 + dd) * SEQLEN + l0 + dloc] = so[dloc][dd];
}

// ---------------------------------------------------------------------------
// Selective scan. Half-warp (16 lanes) per channel, lane = state index s.
// 4096 channels -> 2048 warps -> 256 blocks of 256 threads.
// dt/ut are warp-uniform along l: load as float4 once per 4 steps.
// ---------------------------------------------------------------------------
__global__ __launch_bounds__(256) void scan_kernel(
    const float* __restrict__ deltat, const float* __restrict__ uct,
    const float* __restrict__ xdbl, const float* __restrict__ Alog,
    float* __restrict__ yscant)
{
    const int warp = (blockIdx.x * blockDim.x + threadIdx.x) >> 5;
    const int lane = threadIdx.x & 31;
    const int half = lane >> 4;
    const int s    = lane & 15;
    const int ch   = warp * 2 + half;      // 0..4095
    const int b    = ch >> 9;
    const int d    = ch & 511;

    const float A = -__expf(Alog[d * DSTATE + s]);
    float state = 0.f;

    const float4* dptr4 = (const float4*)(deltat + (size_t)ch * SEQLEN);
    const float4* uptr4 = (const float4*)(uct    + (size_t)ch * SEQLEN);
    const float* xB   = xdbl + (size_t)b * SEQLEN * 48 + 16 + s;
    float* yout = yscant + (size_t)ch * SEQLEN;

    for (int l4 = 0; l4 < SEQLEN / 4; l4++) {
        const float4 dt4 = __ldg(dptr4 + l4);
        const float4 ut4 = __ldg(uptr4 + l4);
        const float dts[4] = {dt4.x, dt4.y, dt4.z, dt4.w};
        const float uts[4] = {ut4.x, ut4.y, ut4.z, ut4.w};
#pragma unroll
        for (int j = 0; j < 4; j++) {
            const float Bv = __ldg(xB);
            const float Cv = __ldg(xB + 16);
            xB += 48;
            const float dA = __expf(dts[j] * A);
            state = fmaf(state, dA, dts[j] * uts[j] * Bv);
            float p = state * Cv;
            p += __shfl_xor_sync(0xffffffffu, p, 8);
            p += __shfl_xor_sync(0xffffffffu, p, 4);
            p += __shfl_xor_sync(0xffffffffu, p, 2);
            p += __shfl_xor_sync(0xffffffffu, p, 1);
            if (s == 0) yout[l4 * 4 + j] = p;
        }
    }
}

// ---------------------------------------------------------------------------
// Gate: y(M,512) = (yscan^T + D*uc) * silu(z)
// ---------------------------------------------------------------------------
__global__ __launch_bounds__(256) void gate_kernel(
    const float* __restrict__ yscant, const float* __restrict__ uc,
    const float* __restrict__ xz, const float* __restrict__ Dw,
    float* __restrict__ y)
{
    __shared__ float s[32][33];
    const int d0 = blockIdx.x * 32;
    const int l0 = blockIdx.y * 32;
    const int b  = blockIdx.z;
    const int tx = threadIdx.x & 31;
    const int ty = threadIdx.x >> 5;

    for (int dd = ty; dd < 32; dd += 8)
        s[dd][tx] = yscant[(size_t)(b * DINNER + d0 + dd) * SEQLEN + l0 + tx];
    __syncthreads();

    const int d = d0 + tx;
    const float Dv = Dw[d];
    for (int ll = ty; ll < 32; ll += 8) {
        const int m = b * SEQLEN + l0 + ll;
        const float ucv = uc[(size_t)m * DINNER + d];
        const float zv  = xz[(size_t)m * 1024 + DINNER + d];
        const float silu_z = zv / (1.f + __expf(-zv));
        y[(size_t)m * DINNER + d] = (s[tx][ll] + Dv * ucv) * silu_z;
    }
}

// ---------------------------------------------------------------------------
// Residual + LayerNorm. Warp per row.
// ---------------------------------------------------------------------------
__global__ __launch_bounds__(256) void ln_kernel(
    const float* __restrict__ outtmp, const float* __restrict__ x,
    const float* __restrict__ g, const float* __restrict__ beta,
    float* __restrict__ out)
{
    const int warp = threadIdx.x >> 5;
    const int lane = threadIdx.x & 31;
    const int row = blockIdx.x * 8 + warp;

    float h[8];
    float sum = 0.f, sq = 0.f;
#pragma unroll
    for (int i = 0; i < 8; i++) {
        const int c = lane + i * 32;
        const float v = outtmp[(size_t)row * 256 + c] + x[(size_t)row * 256 + c];
        h[i] = v; sum += v; sq = fmaf(v, v, sq);
    }
#pragma unroll
    for (int o = 16; o; o >>= 1) {
        sum += __shfl_xor_sync(0xffffffffu, sum, o);
        sq  += __shfl_xor_sync(0xffffffffu, sq,  o);
    }
    const float mu  = sum * (1.f / 256.f);
    const float var = sq * (1.f / 256.f) - mu * mu;
    const float inv = rsqrtf(var + 1e-5f);
#pragma unroll
    for (int i = 0; i < 8; i++) {
        const int c = lane + i * 32;
        out[(size_t)row * 256 + c] = (h[i] - mu) * inv * g[c] + beta[c];
    }
}

// ---------------------------------------------------------------------------
extern "C" void kernel_launch(void* const* d_in, const int* in_sizes, int n_in,
                              void* d_out, int out_size)
{
    const float* x       = (const float*)d_in[0];
    const float* in_w    = (const float*)d_in[1];
    const float* conv_w  = (const float*)d_in[2];
    const float* conv_b  = (const float*)d_in[3];
    const float* xproj_w = (const float*)d_in[4];
    const float* dt_w    = (const float*)d_in[5];
    const float* dt_b    = (const float*)d_in[6];
    const float* A_log   = (const float*)d_in[7];
    const float* Dw      = (const float*)d_in[8];
    const float* out_w   = (const float*)d_in[9];
    const float* ln_g    = (const float*)d_in[10];
    const float* ln_b    = (const float*)d_in[11];
    float* out = (float*)d_out;

    float* base = nullptr;
    cudaGetSymbolAddress((void**)&base, g_scratch);
    float* xz     = base + OFF_XZ;
    float* uc     = base + OFF_UC;
    float* uct    = base + OFF_UCT;
    float* xdbl   = base + OFF_XDBL;
    float* deltat = base + OFF_DELTAT;
    float* yscant = base + OFF_YSCANT;
    float* y      = base + OFF_Y;
    float* outtmp = base + OFF_OUTTMP;

    // 1. in_proj: xz = x @ in_w^T   (M=32768, N=1024, K=256)
    sgemm128_kernel<<<dim3(1024 / 128, MROWS / 128), 256>>>(x, in_w, xz, MROWS, 1024, 256);

    // 2. conv4 + SiLU (+ transpose)
    conv_silu_kernel<<<dim3(DINNER / 32, SEQLEN / 32, BATCH), 256>>>(xz, conv_w, conv_b, uc, uct);

    // 3. x_proj: xdbl = uc @ xproj_w^T   (N=48, K=512)
    sgemm_kernel<<<dim3(1, MROWS / 128), 256>>>(uc, xproj_w, xdbl, MROWS, 48, 512);

    // 4. dt_proj + softplus (transposed write)
    dtproj_kernel<<<dim3(DINNER / 32, MROWS / 32), 256>>>(xdbl, dt_w, dt_b, deltat);

    // 5. selective scan (4096 channels, 2 per warp -> 256 blocks)
    scan_kernel<<<NCH / 16, 256>>>(deltat, uct, xdbl, A_log, yscant);

    // 6. gate + skip
    gate_kernel<<<dim3(DINNER / 32, SEQLEN / 32, BATCH), 256>>>(yscant, uc, xz, Dw, y);

    // 7. out_proj: outtmp = y @ out_w^T   (M=32768, N=256, K=512)
    sgemm128_kernel<<<dim3(256 / 128, MROWS / 128), 256>>>(y, out_w, outtmp, MROWS, 256, 512);

    // 8. residual + LayerNorm
    ln_kernel<<<MROWS / 8, 256>>>(outtmp, x, ln_g, ln_b, out);
}

// round 5
// speedup vs baseline: 1.4666x; 1.1705x over previous
#include <cuda_runtime.h>
#include <cuda_bf16.h>
#include <math.h>
#include <stdint.h>

// ---------------------------------------------------------------------------
// MambaBottleneck: B=8, L=4096, D_MODEL=256, D_INNER=512, D_STATE=16,
// DT_RANK=16, D_CONV=4.  M = B*L = 32768 rows.
// ---------------------------------------------------------------------------

#define BATCH   8
#define SEQLEN  4096
#define DMODEL  256
#define DINNER  512
#define DSTATE  16
#define MROWS   (BATCH * SEQLEN)          // 32768
#define NCH     (BATCH * DINNER)          // 4096

// scratch layout (floats)
#define OFF_XZ      0
#define SZ_XZ       (MROWS * 1024)
#define OFF_UC      (OFF_XZ + SZ_XZ)
#define SZ_UC       (MROWS * DINNER)
#define OFF_UCT     (OFF_UC + SZ_UC)
#define SZ_UCT      (NCH * SEQLEN)
#define OFF_XDBL    (OFF_UCT + SZ_UCT)
#define SZ_XDBL     (MROWS * 48)
#define OFF_DELTAT  (OFF_XDBL + SZ_XDBL)
#define SZ_DELTAT   (NCH * SEQLEN)
#define OFF_YSCANT  (OFF_DELTAT + SZ_DELTAT)
#define SZ_YSCANT   (NCH * SEQLEN)
#define OFF_Y       (OFF_YSCANT + SZ_YSCANT)
#define SZ_Y        (MROWS * DINNER)
#define OFF_OUTTMP  (OFF_Y + SZ_Y)
#define SZ_OUTTMP   (MROWS * DMODEL)
#define SCRATCH_TOTAL (OFF_OUTTMP + SZ_OUTTMP)

static __device__ float g_scratch[SCRATCH_TOTAL];

// ---------------------------------------------------------------------------
// Tensor-core GEMM with bf16 split-precision (hi/lo) accumulation.
// C[M,N] = A[M,K] @ W[N,K]^T, computed as Ah*Bh + Ah*Bl + Al*Bh (fp32 accum).
// Block tile 128x128x32, 8 warps (4 along m, 2 along n), warp tile 32x64.
// Smem stored as bf16x2 pairs with row stride 20 words -> conflict-free
// fragment loads (bank = lane + const for every frag element).
// Requires M%128==0, N%128==0, K%32==0.
// ---------------------------------------------------------------------------
__device__ __forceinline__ void mma_bf16(float* c, const uint32_t* a,
                                         uint32_t b0, uint32_t b1)
{
    asm volatile(
        "mma.sync.aligned.m16n8k16.row.col.f32.bf16.bf16.f32 "
        "{%0,%1,%2,%3}, {%4,%5,%6,%7}, {%8,%9}, {%0,%1,%2,%3};"
        : "+f"(c[0]), "+f"(c[1]), "+f"(c[2]), "+f"(c[3])
        : "r"(a[0]), "r"(a[1]), "r"(a[2]), "r"(a[3]), "r"(b0), "r"(b1));
}

__device__ __forceinline__ void split_pair(float x, float y,
                                           uint32_t& hi, uint32_t& lo)
{
    __nv_bfloat16 hx = __float2bfloat16(x);
    __nv_bfloat16 hy = __float2bfloat16(y);
    __nv_bfloat162 hv; hv.x = hx; hv.y = hy;
    __nv_bfloat162 lv;
    lv.x = __float2bfloat16(x - __bfloat162float(hx));
    lv.y = __float2bfloat16(y - __bfloat162float(hy));
    hi = *reinterpret_cast<uint32_t*>(&hv);
    lo = *reinterpret_cast<uint32_t*>(&lv);
}

#define SPAD 20   // 16 bf16x2 pairs per row + 4-word pad (conflict-free)

__global__ __launch_bounds__(256) void gemm_tc_kernel(
    const float* __restrict__ A, const float* __restrict__ W,
    float* __restrict__ C, int M, int N, int K)
{
    __shared__ uint32_t As_hi[128][SPAD];
    __shared__ uint32_t As_lo[128][SPAD];
    __shared__ uint32_t Ws_hi[128][SPAD];
    __shared__ uint32_t Ws_lo[128][SPAD];

    const int bm = blockIdx.y * 128;
    const int bn = blockIdx.x * 128;
    const int tid = threadIdx.x;
    const int lane = tid & 31;
    const int g   = lane >> 2;     // groupID 0..7
    const int tig = lane & 3;      // thread-in-group 0..3
    const int w   = tid >> 5;
    const int wm  = (w >> 1) * 32; // warp m-offset: 4 warps along m
    const int wn  = (w & 1) * 64;  // warp n-offset: 2 warps along n

    // gmem fill assignment: 16 consecutive floats per thread per operand
    const int frow = tid >> 1;              // 0..127
    const int fcol = (tid & 1) * 16;        // float offset 0 or 16
    const int pbase = (tid & 1) * 8;        // pair offset 0 or 8
    const float* Ap = A + (size_t)(bm + frow) * K + fcol;
    const float* Wp = W + (size_t)(bn + frow) * K + fcol;

    float acc[2][8][4];
#pragma unroll
    for (int i = 0; i < 2; i++)
#pragma unroll
        for (int j = 0; j < 8; j++)
#pragma unroll
            for (int q = 0; q < 4; q++) acc[i][j][q] = 0.f;

    for (int k0 = 0; k0 < K; k0 += 32) {
        // ---- fill smem (convert fp32 -> bf16 hi/lo pairs) ----
#pragma unroll
        for (int v = 0; v < 4; v++) {
            float4 a4 = *(const float4*)(Ap + k0 + v * 4);
            float4 w4 = *(const float4*)(Wp + k0 + v * 4);
            const int p = pbase + 2 * v;
            split_pair(a4.x, a4.y, As_hi[frow][p],     As_lo[frow][p]);
            split_pair(a4.z, a4.w, As_hi[frow][p + 1], As_lo[frow][p + 1]);
            split_pair(w4.x, w4.y, Ws_hi[frow][p],     Ws_lo[frow][p]);
            split_pair(w4.z, w4.w, Ws_hi[frow][p + 1], Ws_lo[frow][p + 1]);
        }
        __syncthreads();

        // ---- mma phase: 2 k-steps of 16 ----
#pragma unroll
        for (int ks = 0; ks < 2; ks++) {
            const int kp = ks * 8 + tig;
            uint32_t ah[2][4], al[2][4];
#pragma unroll
            for (int im = 0; im < 2; im++) {
                const int r = wm + im * 16 + g;
                ah[im][0] = As_hi[r][kp];         al[im][0] = As_lo[r][kp];
                ah[im][1] = As_hi[r + 8][kp];     al[im][1] = As_lo[r + 8][kp];
                ah[im][2] = As_hi[r][kp + 4];     al[im][2] = As_lo[r][kp + 4];
                ah[im][3] = As_hi[r + 8][kp + 4]; al[im][3] = As_lo[r + 8][kp + 4];
            }
#pragma unroll
            for (int jn = 0; jn < 8; jn++) {
                const int nr = wn + jn * 8 + g;
                const uint32_t bh0 = Ws_hi[nr][kp], bh1 = Ws_hi[nr][kp + 4];
                const uint32_t bl0 = Ws_lo[nr][kp], bl1 = Ws_lo[nr][kp + 4];
#pragma unroll
                for (int im = 0; im < 2; im++) {
                    mma_bf16(acc[im][jn], ah[im], bh0, bh1);  // hi*hi
                    mma_bf16(acc[im][jn], ah[im], bl0, bl1);  // hi*lo
                    mma_bf16(acc[im][jn], al[im], bh0, bh1);  // lo*hi
                }
            }
        }
        __syncthreads();
    }

    // ---- epilogue ----
#pragma unroll
    for (int im = 0; im < 2; im++) {
        const int row = bm + wm + im * 16 + g;
#pragma unroll
        for (int jn = 0; jn < 8; jn++) {
            const int col = bn + wn + jn * 8 + 2 * tig;
            float2 v0 = make_float2(acc[im][jn][0], acc[im][jn][1]);
            float2 v1 = make_float2(acc[im][jn][2], acc[im][jn][3]);
            *(float2*)(C + (size_t)row * N + col)       = v0;
            *(float2*)(C + (size_t)(row + 8) * N + col) = v1;
        }
    }
}

// ---------------------------------------------------------------------------
// SGEMM 128x64x16 (for x_proj, N=48 with guard).
// ---------------------------------------------------------------------------
__global__ __launch_bounds__(256) void sgemm_kernel(
    const float* __restrict__ A, const float* __restrict__ W,
    float* __restrict__ C, int M, int N, int K)
{
    __shared__ float As[16 * 128];
    __shared__ float Bs[16 * 64];

    const int bm = blockIdx.y * 128;
    const int bn = blockIdx.x * 64;
    const int tid = threadIdx.x;
    const int tx = tid & 15;
    const int ty = tid >> 4;

    float acc[8][4];
#pragma unroll
    for (int i = 0; i < 8; i++)
#pragma unroll
        for (int j = 0; j < 4; j++) acc[i][j] = 0.f;

    const int ar = tid >> 1, ak = (tid & 1) * 8;
    const int br = tid >> 2, bk = (tid & 3) * 4;
    const bool bval = (bn + br) < N;

    const float* Ap = A + (size_t)(bm + ar) * K + ak;
    const float* Wp = W + (size_t)(bval ? (bn + br) : 0) * K + bk;

    for (int k0 = 0; k0 < K; k0 += 16) {
        float4 a0 = *(const float4*)(Ap + k0);
        float4 a1 = *(const float4*)(Ap + k0 + 4);
        float4 bv = *(const float4*)(Wp + k0);
        if (!bval) { bv.x = bv.y = bv.z = bv.w = 0.f; }

        As[(ak + 0) * 128 + ar] = a0.x;
        As[(ak + 1) * 128 + ar] = a0.y;
        As[(ak + 2) * 128 + ar] = a0.z;
        As[(ak + 3) * 128 + ar] = a0.w;
        As[(ak + 4) * 128 + ar] = a1.x;
        As[(ak + 5) * 128 + ar] = a1.y;
        As[(ak + 6) * 128 + ar] = a1.z;
        As[(ak + 7) * 128 + ar] = a1.w;
        Bs[(bk + 0) * 64 + br] = bv.x;
        Bs[(bk + 1) * 64 + br] = bv.y;
        Bs[(bk + 2) * 64 + br] = bv.z;
        Bs[(bk + 3) * 64 + br] = bv.w;
        __syncthreads();

#pragma unroll
        for (int kk = 0; kk < 16; kk++) {
            float4 av0 = *(const float4*)&As[kk * 128 + ty * 8];
            float4 av1 = *(const float4*)&As[kk * 128 + ty * 8 + 4];
            float4 bv4 = *(const float4*)&Bs[kk * 64 + tx * 4];
            float a[8] = {av0.x, av0.y, av0.z, av0.w, av1.x, av1.y, av1.z, av1.w};
            float b[4] = {bv4.x, bv4.y, bv4.z, bv4.w};
#pragma unroll
            for (int i = 0; i < 8; i++)
#pragma unroll
                for (int j = 0; j < 4; j++)
                    acc[i][j] = fmaf(a[i], b[j], acc[i][j]);
        }
        __syncthreads();
    }

#pragma unroll
    for (int i = 0; i < 8; i++) {
        const int row = bm + ty * 8 + i;
#pragma unroll
        for (int j = 0; j < 4; j++) {
            const int col = bn + tx * 4 + j;
            if (col < N) C[(size_t)row * N + col] = acc[i][j];
        }
    }
}

// ---------------------------------------------------------------------------
// Depthwise causal conv4 + SiLU. Writes uc (M,512) and uct (CH,L).
// ---------------------------------------------------------------------------
__global__ __launch_bounds__(256) void conv_silu_kernel(
    const float* __restrict__ xz, const float* __restrict__ cw,
    const float* __restrict__ cb, float* __restrict__ uc,
    float* __restrict__ uct)
{
    __shared__ float su[35][33];
    __shared__ float so[32][33];
    const int d0 = blockIdx.x * 32;
    const int l0 = blockIdx.y * 32;
    const int b  = blockIdx.z;
    const int tx = threadIdx.x & 31;
    const int ty = threadIdx.x >> 5;

    for (int r = ty; r < 35; r += 8) {
        const int l = l0 - 3 + r;
        float v = 0.f;
        if (l >= 0) v = xz[(size_t)(b * SEQLEN + l) * 1024 + d0 + tx];
        su[r][tx] = v;
    }
    __syncthreads();

    const int d = d0 + tx;
    const float w0 = cw[d * 4 + 0], w1 = cw[d * 4 + 1];
    const float w2 = cw[d * 4 + 2], w3 = cw[d * 4 + 3];
    const float bb = cb[d];

    for (int ll = ty; ll < 32; ll += 8) {
        float acc = su[ll][tx] * w0 + su[ll + 1][tx] * w1
                  + su[ll + 2][tx] * w2 + su[ll + 3][tx] * w3 + bb;
        const float sv = acc / (1.f + __expf(-acc));
        const int m = b * SEQLEN + l0 + ll;
        uc[(size_t)m * DINNER + d] = sv;
        so[ll][tx] = sv;
    }
    __syncthreads();

    for (int dd = ty; dd < 32; dd += 8)
        uct[(size_t)(b * DINNER + d0 + dd) * SEQLEN + l0 + tx] = so[tx][dd];
}

// ---------------------------------------------------------------------------
// delta_t(CH,L) = softplus(xdbl[:, 0:16] @ dt_proj_w^T + dt_proj_b)
// ---------------------------------------------------------------------------
__global__ __launch_bounds__(256) void dtproj_kernel(
    const float* __restrict__ xdbl, const float* __restrict__ dtw,
    const float* __restrict__ dtb, float* __restrict__ deltat)
{
    __shared__ float sdt[32][17];
    __shared__ float sw[32][17];
    __shared__ float so[32][33];
    const int d0 = blockIdx.x * 32;
    const int m0 = blockIdx.y * 32;
    const int tid = threadIdx.x;

    {
        const int r = tid >> 4, c = tid & 15;
        sdt[r][c]      = xdbl[(size_t)(m0 + r) * 48 + c];
        sdt[r + 16][c] = xdbl[(size_t)(m0 + r + 16) * 48 + c];
        sw[r][c]       = dtw[(d0 + r) * 16 + c];
        sw[r + 16][c]  = dtw[(d0 + r + 16) * 16 + c];
    }
    __syncthreads();

    const int dloc = tid & 31;
    const float bias = dtb[d0 + dloc];
    for (int ll = tid >> 5; ll < 32; ll += 8) {
        float acc = bias;
#pragma unroll
        for (int k = 0; k < 16; k++) acc = fmaf(sdt[ll][k], sw[dloc][k], acc);
        so[ll][dloc] = fmaxf(acc, 0.f) + __logf(1.f + __expf(-fabsf(acc)));
    }
    __syncthreads();

    const int b  = m0 / SEQLEN;
    const int l0 = m0 % SEQLEN;
    for (int dd = tid >> 5; dd < 32; dd += 8)
        deltat[(size_t)(b * DINNER + d0 + dd) * SEQLEN + l0 + dloc] = so[dloc][dd];
}

// ---------------------------------------------------------------------------
// Selective scan. Half-warp (16 lanes) per channel, lane = state index s.
// 4096 channels -> 2048 warps -> 256 blocks of 256 threads.
// ---------------------------------------------------------------------------
__global__ __launch_bounds__(256) void scan_kernel(
    const float* __restrict__ deltat, const float* __restrict__ uct,
    const float* __restrict__ xdbl, const float* __restrict__ Alog,
    float* __restrict__ yscant)
{
    const int warp = (blockIdx.x * blockDim.x + threadIdx.x) >> 5;
    const int lane = threadIdx.x & 31;
    const int half = lane >> 4;
    const int s    = lane & 15;
    const int ch   = warp * 2 + half;      // 0..4095
    const int b    = ch >> 9;
    const int d    = ch & 511;

    const float A = -__expf(Alog[d * DSTATE + s]);
    float state = 0.f;

    const float4* dptr4 = (const float4*)(deltat + (size_t)ch * SEQLEN);
    const float4* uptr4 = (const float4*)(uct    + (size_t)ch * SEQLEN);
    const float* xB   = xdbl + (size_t)b * SEQLEN * 48 + 16 + s;
    float* yout = yscant + (size_t)ch * SEQLEN;

    for (int l4 = 0; l4 < SEQLEN / 4; l4++) {
        const float4 dt4 = __ldg(dptr4 + l4);
        const float4 ut4 = __ldg(uptr4 + l4);
        const float dts[4] = {dt4.x, dt4.y, dt4.z, dt4.w};
        const float uts[4] = {ut4.x, ut4.y, ut4.z, ut4.w};
#pragma unroll
        for (int j = 0; j < 4; j++) {
            const float Bv = __ldg(xB);
            const float Cv = __ldg(xB + 16);
            xB += 48;
            const float dA = __expf(dts[j] * A);
            state = fmaf(state, dA, dts[j] * uts[j] * Bv);
            float p = state * Cv;
            p += __shfl_xor_sync(0xffffffffu, p, 8);
            p += __shfl_xor_sync(0xffffffffu, p, 4);
            p += __shfl_xor_sync(0xffffffffu, p, 2);
            p += __shfl_xor_sync(0xffffffffu, p, 1);
            if (s == 0) yout[l4 * 4 + j] = p;
        }
    }
}

// ---------------------------------------------------------------------------
// Gate: y(M,512) = (yscan^T + D*uc) * silu(z)
// ---------------------------------------------------------------------------
__global__ __launch_bounds__(256) void gate_kernel(
    const float* __restrict__ yscant, const float* __restrict__ uc,
    const float* __restrict__ xz, const float* __restrict__ Dw,
    float* __restrict__ y)
{
    __shared__ float s[32][33];
    const int d0 = blockIdx.x * 32;
    const int l0 = blockIdx.y * 32;
    const int b  = blockIdx.z;
    const int tx = threadIdx.x & 31;
    const int ty = threadIdx.x >> 5;

    for (int dd = ty; dd < 32; dd += 8)
        s[dd][tx] = yscant[(size_t)(b * DINNER + d0 + dd) * SEQLEN + l0 + tx];
    __syncthreads();

    const int d = d0 + tx;
    const float Dv = Dw[d];
    for (int ll = ty; ll < 32; ll += 8) {
        const int m = b * SEQLEN + l0 + ll;
        const float ucv = uc[(size_t)m * DINNER + d];
        const float zv  = xz[(size_t)m * 1024 + DINNER + d];
        const float silu_z = zv / (1.f + __expf(-zv));
        y[(size_t)m * DINNER + d] = (s[tx][ll] + Dv * ucv) * silu_z;
    }
}

// ---------------------------------------------------------------------------
// Residual + LayerNorm. Warp per row.
// ---------------------------------------------------------------------------
__global__ __launch_bounds__(256) void ln_kernel(
    const float* __restrict__ outtmp, const float* __restrict__ x,
    const float* __restrict__ g, const float* __restrict__ beta,
    float* __restrict__ out)
{
    const int warp = threadIdx.x >> 5;
    const int lane = threadIdx.x & 31;
    const int row = blockIdx.x * 8 + warp;

    float h[8];
    float sum = 0.f, sq = 0.f;
#pragma unroll
    for (int i = 0; i < 8; i++) {
        const int c = lane + i * 32;
        const float v = outtmp[(size_t)row * 256 + c] + x[(size_t)row * 256 + c];
        h[i] = v; sum += v; sq = fmaf(v, v, sq);
    }
#pragma unroll
    for (int o = 16; o; o >>= 1) {
        sum += __shfl_xor_sync(0xffffffffu, sum, o);
        sq  += __shfl_xor_sync(0xffffffffu, sq,  o);
    }
    const float mu  = sum * (1.f / 256.f);
    const float var = sq * (1.f / 256.f) - mu * mu;
    const float inv = rsqrtf(var + 1e-5f);
#pragma unroll
    for (int i = 0; i < 8; i++) {
        const int c = lane + i * 32;
        out[(size_t)row * 256 + c] = (h[i] - mu) * inv * g[c] + beta[c];
    }
}

// ---------------------------------------------------------------------------
extern "C" void kernel_launch(void* const* d_in, const int* in_sizes, int n_in,
                              void* d_out, int out_size)
{
    const float* x       = (const float*)d_in[0];
    const float* in_w    = (const float*)d_in[1];
    const float* conv_w  = (const float*)d_in[2];
    const float* conv_b  = (const float*)d_in[3];
    const float* xproj_w = (const float*)d_in[4];
    const float* dt_w    = (const float*)d_in[5];
    const float* dt_b    = (const float*)d_in[6];
    const float* A_log   = (const float*)d_in[7];
    const float* Dw      = (const float*)d_in[8];
    const float* out_w   = (const float*)d_in[9];
    const float* ln_g    = (const float*)d_in[10];
    const float* ln_b    = (const float*)d_in[11];
    float* out = (float*)d_out;

    float* base = nullptr;
    cudaGetSymbolAddress((void**)&base, g_scratch);
    float* xz     = base + OFF_XZ;
    float* uc     = base + OFF_UC;
    float* uct    = base + OFF_UCT;
    float* xdbl   = base + OFF_XDBL;
    float* deltat = base + OFF_DELTAT;
    float* yscant = base + OFF_YSCANT;
    float* y      = base + OFF_Y;
    float* outtmp = base + OFF_OUTTMP;

    // 1. in_proj: xz = x @ in_w^T   (M=32768, N=1024, K=256) [tensor cores]
    gemm_tc_kernel<<<dim3(1024 / 128, MROWS / 128), 256>>>(x, in_w, xz, MROWS, 1024, 256);

    // 2. conv4 + SiLU (+ transpose)
    conv_silu_kernel<<<dim3(DINNER / 32, SEQLEN / 32, BATCH), 256>>>(xz, conv_w, conv_b, uc, uct);

    // 3. x_proj: xdbl = uc @ xproj_w^T   (N=48, K=512)
    sgemm_kernel<<<dim3(1, MROWS / 128), 256>>>(uc, xproj_w, xdbl, MROWS, 48, 512);

    // 4. dt_proj + softplus (transposed write)
    dtproj_kernel<<<dim3(DINNER / 32, MROWS / 32), 256>>>(xdbl, dt_w, dt_b, deltat);

    // 5. selective scan (4096 channels, 2 per warp -> 256 blocks)
    scan_kernel<<<NCH / 16, 256>>>(deltat, uct, xdbl, A_log, yscant);

    // 6. gate + skip
    gate_kernel<<<dim3(DINNER / 32, SEQLEN / 32, BATCH), 256>>>(yscant, uc, xz, Dw, y);

    // 7. out_proj: outtmp = y @ out_w^T   (M=32768, N=256, K=512) [tensor cores]
    gemm_tc_kernel<<<dim3(256 / 128, MROWS / 128), 256>>>(y, out_w, outtmp, MROWS, 256, 512);

    // 8. residual + LayerNorm
    ln_kernel<<<MROWS / 8, 256>>>(outtmp, x, ln_g, ln_b, out);
}

// round 6
// speedup vs baseline: 1.4703x; 1.0026x over previous
#include <cuda_runtime.h>
#include <cuda_bf16.h>
#include <math.h>
#include <stdint.h>

// ---------------------------------------------------------------------------
// MambaBottleneck: B=8, L=4096, D_MODEL=256, D_INNER=512, D_STATE=16,
// DT_RANK=16, D_CONV=4.  M = B*L = 32768 rows.
// ---------------------------------------------------------------------------

#define BATCH   8
#define SEQLEN  4096
#define DMODEL  256
#define DINNER  512
#define DSTATE  16
#define MROWS   (BATCH * SEQLEN)          // 32768
#define NCH     (BATCH * DINNER)          // 4096

// scratch layout (float units; bf16 arrays use half-sized float counts)
#define OFF_XZ      0
#define SZ_XZ       (MROWS * 1024)
#define OFF_UC      (OFF_XZ + SZ_XZ)
#define SZ_UC       (MROWS * DINNER)
#define OFF_UCT     (OFF_UC + SZ_UC)
#define SZ_UCT      (NCH * SEQLEN)
#define OFF_XDBL    (OFF_UCT + SZ_UCT)
#define SZ_XDBL     (MROWS * 48)
#define OFF_DELTAT  (OFF_XDBL + SZ_XDBL)
#define SZ_DELTAT   (NCH * SEQLEN)
#define OFF_YSCANT  (OFF_DELTAT + SZ_DELTAT)
#define SZ_YSCANT   (NCH * SEQLEN)
#define OFF_OUTTMP  (OFF_YSCANT + SZ_YSCANT)
#define SZ_OUTTMP   (MROWS * DMODEL)
#define OFF_XH      (OFF_OUTTMP + SZ_OUTTMP)
#define SZ_XH       (MROWS * DMODEL / 2)
#define OFF_XL      (OFF_XH + SZ_XH)
#define OFF_YH      (OFF_XL + SZ_XH)
#define SZ_YH       (MROWS * DINNER / 2)
#define OFF_YL      (OFF_YH + SZ_YH)
#define OFF_WIH     (OFF_YL + SZ_YH)
#define SZ_WIH      (1024 * DMODEL / 2)
#define OFF_WIL     (OFF_WIH + SZ_WIH)
#define OFF_WOH     (OFF_WIL + SZ_WIH)
#define SZ_WOH      (DMODEL * DINNER / 2)
#define OFF_WOL     (OFF_WOH + SZ_WOH)
#define SCRATCH_TOTAL (OFF_WOL + SZ_WOH)

static __device__ float g_scratch[SCRATCH_TOTAL];

// ---------------------------------------------------------------------------
// fp32 -> bf16 hi/lo split (vectorized float4 -> 2x uint2)
// ---------------------------------------------------------------------------
__global__ __launch_bounds__(256) void split_kernel(
    const float4* __restrict__ src, uint2* __restrict__ h,
    uint2* __restrict__ l, int n4)
{
    const int i = blockIdx.x * blockDim.x + threadIdx.x;
    if (i >= n4) return;
    const float4 v = src[i];
    __nv_bfloat162 h0, h1, l0, l1;
    h0.x = __float2bfloat16(v.x); h0.y = __float2bfloat16(v.y);
    h1.x = __float2bfloat16(v.z); h1.y = __float2bfloat16(v.w);
    l0.x = __float2bfloat16(v.x - __bfloat162float(h0.x));
    l0.y = __float2bfloat16(v.y - __bfloat162float(h0.y));
    l1.x = __float2bfloat16(v.z - __bfloat162float(h1.x));
    l1.y = __float2bfloat16(v.w - __bfloat162float(h1.y));
    h[i] = make_uint2(*(uint32_t*)&h0, *(uint32_t*)&h1);
    l[i] = make_uint2(*(uint32_t*)&l0, *(uint32_t*)&l1);
}

// ---------------------------------------------------------------------------
// Tensor-core GEMM, pre-split bf16 inputs. C = A @ W^T (fp32 out).
// acc = Ah*Wh + Ah*Wl + Al*Wh. Block 128x128x32, 8 warps (4m x 2n),
// warp tile 32x64. Smem bf16x2 pairs, row stride 20 words (conflict-free).
// Register-staged prefetch of next k-tile overlaps gmem with mma.
// ---------------------------------------------------------------------------
__device__ __forceinline__ void mma_bf16(float* c, const uint32_t* a,
                                         uint32_t b0, uint32_t b1)
{
    asm volatile(
        "mma.sync.aligned.m16n8k16.row.col.f32.bf16.bf16.f32 "
        "{%0,%1,%2,%3}, {%4,%5,%6,%7}, {%8,%9}, {%0,%1,%2,%3};"
        : "+f"(c[0]), "+f"(c[1]), "+f"(c[2]), "+f"(c[3])
        : "r"(a[0]), "r"(a[1]), "r"(a[2]), "r"(a[3]), "r"(b0), "r"(b1));
}

#define SPAD 20

__global__ __launch_bounds__(256) void gemm_tc2_kernel(
    const __nv_bfloat16* __restrict__ Ah_, const __nv_bfloat16* __restrict__ Al_,
    const __nv_bfloat16* __restrict__ Wh_, const __nv_bfloat16* __restrict__ Wl_,
    float* __restrict__ C, int M, int N, int K)
{
    __shared__ uint32_t sAh[128][SPAD];
    __shared__ uint32_t sAl[128][SPAD];
    __shared__ uint32_t sWh[128][SPAD];
    __shared__ uint32_t sWl[128][SPAD];

    const int bm = blockIdx.y * 128;
    const int bn = blockIdx.x * 128;
    const int tid = threadIdx.x;
    const int lane = tid & 31;
    const int g   = lane >> 2;
    const int tig = lane & 3;
    const int w   = tid >> 5;
    const int wm  = (w >> 1) * 32;
    const int wn  = (w & 1) * 64;

    const int frow = tid >> 1;          // 0..127
    const int fcol = (tid & 1) * 16;    // bf16 element offset within k-tile
    const int pbase = (tid & 1) * 8;    // pair/word offset

    const __nv_bfloat16* pAh = Ah_ + (size_t)(bm + frow) * K + fcol;
    const __nv_bfloat16* pAl = Al_ + (size_t)(bm + frow) * K + fcol;
    const __nv_bfloat16* pWh = Wh_ + (size_t)(bn + frow) * K + fcol;
    const __nv_bfloat16* pWl = Wl_ + (size_t)(bn + frow) * K + fcol;

    float acc[2][8][4];
#pragma unroll
    for (int i = 0; i < 2; i++)
#pragma unroll
        for (int j = 0; j < 8; j++)
#pragma unroll
            for (int q = 0; q < 4; q++) acc[i][j][q] = 0.f;

    const int KT = K >> 5;

    uint4 vah0, vah1, val0, val1, vwh0, vwh1, vwl0, vwl1;
    vah0 = *(const uint4*)(pAh); vah1 = *(const uint4*)(pAh + 8);
    val0 = *(const uint4*)(pAl); val1 = *(const uint4*)(pAl + 8);
    vwh0 = *(const uint4*)(pWh); vwh1 = *(const uint4*)(pWh + 8);
    vwl0 = *(const uint4*)(pWl); vwl1 = *(const uint4*)(pWl + 8);

    *(uint4*)&sAh[frow][pbase] = vah0; *(uint4*)&sAh[frow][pbase + 4] = vah1;
    *(uint4*)&sAl[frow][pbase] = val0; *(uint4*)&sAl[frow][pbase + 4] = val1;
    *(uint4*)&sWh[frow][pbase] = vwh0; *(uint4*)&sWh[frow][pbase + 4] = vwh1;
    *(uint4*)&sWl[frow][pbase] = vwl0; *(uint4*)&sWl[frow][pbase + 4] = vwl1;
    __syncthreads();

    for (int kt = 0; kt < KT; kt++) {
        if (kt + 1 < KT) {
            const int o = (kt + 1) * 32;
            vah0 = *(const uint4*)(pAh + o); vah1 = *(const uint4*)(pAh + o + 8);
            val0 = *(const uint4*)(pAl + o); val1 = *(const uint4*)(pAl + o + 8);
            vwh0 = *(const uint4*)(pWh + o); vwh1 = *(const uint4*)(pWh + o + 8);
            vwl0 = *(const uint4*)(pWl + o); vwl1 = *(const uint4*)(pWl + o + 8);
        }

#pragma unroll
        for (int ks = 0; ks < 2; ks++) {
            const int kp = ks * 8 + tig;
            uint32_t ah[2][4], al[2][4];
#pragma unroll
            for (int im = 0; im < 2; im++) {
                const int r = wm + im * 16 + g;
                ah[im][0] = sAh[r][kp];         al[im][0] = sAl[r][kp];
                ah[im][1] = sAh[r + 8][kp];     al[im][1] = sAl[r + 8][kp];
                ah[im][2] = sAh[r][kp + 4];     al[im][2] = sAl[r][kp + 4];
                ah[im][3] = sAh[r + 8][kp + 4]; al[im][3] = sAl[r + 8][kp + 4];
            }
#pragma unroll
            for (int jn = 0; jn < 8; jn++) {
                const int nr = wn + jn * 8 + g;
                const uint32_t bh0 = sWh[nr][kp], bh1 = sWh[nr][kp + 4];
                const uint32_t bl0 = sWl[nr][kp], bl1 = sWl[nr][kp + 4];
#pragma unroll
                for (int im = 0; im < 2; im++) {
                    mma_bf16(acc[im][jn], ah[im], bh0, bh1);  // hi*hi
                    mma_bf16(acc[im][jn], ah[im], bl0, bl1);  // hi*lo
                    mma_bf16(acc[im][jn], al[im], bh0, bh1);  // lo*hi
                }
            }
        }
        __syncthreads();

        if (kt + 1 < KT) {
            *(uint4*)&sAh[frow][pbase] = vah0; *(uint4*)&sAh[frow][pbase + 4] = vah1;
            *(uint4*)&sAl[frow][pbase] = val0; *(uint4*)&sAl[frow][pbase + 4] = val1;
            *(uint4*)&sWh[frow][pbase] = vwh0; *(uint4*)&sWh[frow][pbase + 4] = vwh1;
            *(uint4*)&sWl[frow][pbase] = vwl0; *(uint4*)&sWl[frow][pbase + 4] = vwl1;
            __syncthreads();
        }
    }

#pragma unroll
    for (int im = 0; im < 2; im++) {
        const int row = bm + wm + im * 16 + g;
#pragma unroll
        for (int jn = 0; jn < 8; jn++) {
            const int col = bn + wn + jn * 8 + 2 * tig;
            float2 v0 = make_float2(acc[im][jn][0], acc[im][jn][1]);
            float2 v1 = make_float2(acc[im][jn][2], acc[im][jn][3]);
            *(float2*)(C + (size_t)row * N + col)       = v0;
            *(float2*)(C + (size_t)(row + 8) * N + col) = v1;
        }
    }
}

// ---------------------------------------------------------------------------
// SGEMM 128x64x16 (for x_proj, N=48 with guard).
// ---------------------------------------------------------------------------
__global__ __launch_bounds__(256) void sgemm_kernel(
    const float* __restrict__ A, const float* __restrict__ W,
    float* __restrict__ C, int M, int N, int K)
{
    __shared__ float As[16 * 128];
    __shared__ float Bs[16 * 64];

    const int bm = blockIdx.y * 128;
    const int bn = blockIdx.x * 64;
    const int tid = threadIdx.x;
    const int tx = tid & 15;
    const int ty = tid >> 4;

    float acc[8][4];
#pragma unroll
    for (int i = 0; i < 8; i++)
#pragma unroll
        for (int j = 0; j < 4; j++) acc[i][j] = 0.f;

    const int ar = tid >> 1, ak = (tid & 1) * 8;
    const int br = tid >> 2, bk = (tid & 3) * 4;
    const bool bval = (bn + br) < N;

    const float* Ap = A + (size_t)(bm + ar) * K + ak;
    const float* Wp = W + (size_t)(bval ? (bn + br) : 0) * K + bk;

    for (int k0 = 0; k0 < K; k0 += 16) {
        float4 a0 = *(const float4*)(Ap + k0);
        float4 a1 = *(const float4*)(Ap + k0 + 4);
        float4 bv = *(const float4*)(Wp + k0);
        if (!bval) { bv.x = bv.y = bv.z = bv.w = 0.f; }

        As[(ak + 0) * 128 + ar] = a0.x;
        As[(ak + 1) * 128 + ar] = a0.y;
        As[(ak + 2) * 128 + ar] = a0.z;
        As[(ak + 3) * 128 + ar] = a0.w;
        As[(ak + 4) * 128 + ar] = a1.x;
        As[(ak + 5) * 128 + ar] = a1.y;
        As[(ak + 6) * 128 + ar] = a1.z;
        As[(ak + 7) * 128 + ar] = a1.w;
        Bs[(bk + 0) * 64 + br] = bv.x;
        Bs[(bk + 1) * 64 + br] = bv.y;
        Bs[(bk + 2) * 64 + br] = bv.z;
        Bs[(bk + 3) * 64 + br] = bv.w;
        __syncthreads();

#pragma unroll
        for (int kk = 0; kk < 16; kk++) {
            float4 av0 = *(const float4*)&As[kk * 128 + ty * 8];
            float4 av1 = *(const float4*)&As[kk * 128 + ty * 8 + 4];
            float4 bv4 = *(const float4*)&Bs[kk * 64 + tx * 4];
            float a[8] = {av0.x, av0.y, av0.z, av0.w, av1.x, av1.y, av1.z, av1.w};
            float b[4] = {bv4.x, bv4.y, bv4.z, bv4.w};
#pragma unroll
            for (int i = 0; i < 8; i++)
#pragma unroll
                for (int j = 0; j < 4; j++)
                    acc[i][j] = fmaf(a[i], b[j], acc[i][j]);
        }
        __syncthreads();
    }

#pragma unroll
    for (int i = 0; i < 8; i++) {
        const int row = bm + ty * 8 + i;
#pragma unroll
        for (int j = 0; j < 4; j++) {
            const int col = bn + tx * 4 + j;
            if (col < N) C[(size_t)row * N + col] = acc[i][j];
        }
    }
}

// ---------------------------------------------------------------------------
// Depthwise causal conv4 + SiLU. Writes uc (M,512) and uct (CH,L).
// ---------------------------------------------------------------------------
__global__ __launch_bounds__(256) void conv_silu_kernel(
    const float* __restrict__ xz, const float* __restrict__ cw,
    const float* __restrict__ cb, float* __restrict__ uc,
    float* __restrict__ uct)
{
    __shared__ float su[35][33];
    __shared__ float so[32][33];
    const int d0 = blockIdx.x * 32;
    const int l0 = blockIdx.y * 32;
    const int b  = blockIdx.z;
    const int tx = threadIdx.x & 31;
    const int ty = threadIdx.x >> 5;

    for (int r = ty; r < 35; r += 8) {
        const int l = l0 - 3 + r;
        float v = 0.f;
        if (l >= 0) v = xz[(size_t)(b * SEQLEN + l) * 1024 + d0 + tx];
        su[r][tx] = v;
    }
    __syncthreads();

    const int d = d0 + tx;
    const float w0 = cw[d * 4 + 0], w1 = cw[d * 4 + 1];
    const float w2 = cw[d * 4 + 2], w3 = cw[d * 4 + 3];
    const float bb = cb[d];

    for (int ll = ty; ll < 32; ll += 8) {
        float acc = su[ll][tx] * w0 + su[ll + 1][tx] * w1
                  + su[ll + 2][tx] * w2 + su[ll + 3][tx] * w3 + bb;
        const float sv = acc / (1.f + __expf(-acc));
        const int m = b * SEQLEN + l0 + ll;
        uc[(size_t)m * DINNER + d] = sv;
        so[ll][tx] = sv;
    }
    __syncthreads();

    for (int dd = ty; dd < 32; dd += 8)
        uct[(size_t)(b * DINNER + d0 + dd) * SEQLEN + l0 + tx] = so[tx][dd];
}

// ---------------------------------------------------------------------------
// delta_t(CH,L) = softplus(xdbl[:, 0:16] @ dt_proj_w^T + dt_proj_b)
// ---------------------------------------------------------------------------
__global__ __launch_bounds__(256) void dtproj_kernel(
    const float* __restrict__ xdbl, const float* __restrict__ dtw,
    const float* __restrict__ dtb, float* __restrict__ deltat)
{
    __shared__ float sdt[32][17];
    __shared__ float sw[32][17];
    __shared__ float so[32][33];
    const int d0 = blockIdx.x * 32;
    const int m0 = blockIdx.y * 32;
    const int tid = threadIdx.x;

    {
        const int r = tid >> 4, c = tid & 15;
        sdt[r][c]      = xdbl[(size_t)(m0 + r) * 48 + c];
        sdt[r + 16][c] = xdbl[(size_t)(m0 + r + 16) * 48 + c];
        sw[r][c]       = dtw[(d0 + r) * 16 + c];
        sw[r + 16][c]  = dtw[(d0 + r + 16) * 16 + c];
    }
    __syncthreads();

    const int dloc = tid & 31;
    const float bias = dtb[d0 + dloc];
    for (int ll = tid >> 5; ll < 32; ll += 8) {
        float acc = bias;
#pragma unroll
        for (int k = 0; k < 16; k++) acc = fmaf(sdt[ll][k], sw[dloc][k], acc);
        so[ll][dloc] = fmaxf(acc, 0.f) + __logf(1.f + __expf(-fabsf(acc)));
    }
    __syncthreads();

    const int b  = m0 / SEQLEN;
    const int l0 = m0 % SEQLEN;
    for (int dd = tid >> 5; dd < 32; dd += 8)
        deltat[(size_t)(b * DINNER + d0 + dd) * SEQLEN + l0 + dloc] = so[dloc][dd];
}

// ---------------------------------------------------------------------------
// Selective scan. Half-warp (16 lanes) per channel, lane = state index s.
// ---------------------------------------------------------------------------
__global__ __launch_bounds__(256) void scan_kernel(
    const float* __restrict__ deltat, const float* __restrict__ uct,
    const float* __restrict__ xdbl, const float* __restrict__ Alog,
    float* __restrict__ yscant)
{
    const int warp = (blockIdx.x * blockDim.x + threadIdx.x) >> 5;
    const int lane = threadIdx.x & 31;
    const int half = lane >> 4;
    const int s    = lane & 15;
    const int ch   = warp * 2 + half;      // 0..4095
    const int b    = ch >> 9;
    const int d    = ch & 511;

    const float A = -__expf(Alog[d * DSTATE + s]);
    float state = 0.f;

    const float4* dptr4 = (const float4*)(deltat + (size_t)ch * SEQLEN);
    const float4* uptr4 = (const float4*)(uct    + (size_t)ch * SEQLEN);
    const float* xB   = xdbl + (size_t)b * SEQLEN * 48 + 16 + s;
    float* yout = yscant + (size_t)ch * SEQLEN;

    for (int l4 = 0; l4 < SEQLEN / 4; l4++) {
        const float4 dt4 = __ldg(dptr4 + l4);
        const float4 ut4 = __ldg(uptr4 + l4);
        const float dts[4] = {dt4.x, dt4.y, dt4.z, dt4.w};
        const float uts[4] = {ut4.x, ut4.y, ut4.z, ut4.w};
#pragma unroll
        for (int j = 0; j < 4; j++) {
            const float Bv = __ldg(xB);
            const float Cv = __ldg(xB + 16);
            xB += 48;
            const float dA = __expf(dts[j] * A);
            state = fmaf(state, dA, dts[j] * uts[j] * Bv);
            float p = state * Cv;
            p += __shfl_xor_sync(0xffffffffu, p, 8);
            p += __shfl_xor_sync(0xffffffffu, p, 4);
            p += __shfl_xor_sync(0xffffffffu, p, 2);
            p += __shfl_xor_sync(0xffffffffu, p, 1);
            if (s == 0) yout[l4 * 4 + j] = p;
        }
    }
}

// ---------------------------------------------------------------------------
// Gate: y = (yscan^T + D*uc) * silu(z), written as bf16 hi/lo splits.
// ---------------------------------------------------------------------------
__global__ __launch_bounds__(256) void gate_kernel(
    const float* __restrict__ yscant, const float* __restrict__ uc,
    const float* __restrict__ xz, const float* __restrict__ Dw,
    __nv_bfloat16* __restrict__ yh, __nv_bfloat16* __restrict__ yl)
{
    __shared__ float s[32][33];
    const int d0 = blockIdx.x * 32;
    const int l0 = blockIdx.y * 32;
    const int b  = blockIdx.z;
    const int tx = threadIdx.x & 31;
    const int ty = threadIdx.x >> 5;

    for (int dd = ty; dd < 32; dd += 8)
        s[dd][tx] = yscant[(size_t)(b * DINNER + d0 + dd) * SEQLEN + l0 + tx];
    __syncthreads();

    const int d = d0 + tx;
    const float Dv = Dw[d];
    for (int ll = ty; ll < 32; ll += 8) {
        const int m = b * SEQLEN + l0 + ll;
        const float ucv = uc[(size_t)m * DINNER + d];
        const float zv  = xz[(size_t)m * 1024 + DINNER + d];
        const float silu_z = zv / (1.f + __expf(-zv));
        const float v = (s[tx][ll] + Dv * ucv) * silu_z;
        const __nv_bfloat16 hv = __float2bfloat16(v);
        yh[(size_t)m * DINNER + d] = hv;
        yl[(size_t)m * DINNER + d] = __float2bfloat16(v - __bfloat162float(hv));
    }
}

// ---------------------------------------------------------------------------
// Residual + LayerNorm. Warp per row.
// ---------------------------------------------------------------------------
__global__ __launch_bounds__(256) void ln_kernel(
    const float* __restrict__ outtmp, const float* __restrict__ x,
    const float* __restrict__ g, const float* __restrict__ beta,
    float* __restrict__ out)
{
    const int warp = threadIdx.x >> 5;
    const int lane = threadIdx.x & 31;
    const int row = blockIdx.x * 8 + warp;

    float h[8];
    float sum = 0.f, sq = 0.f;
#pragma unroll
    for (int i = 0; i < 8; i++) {
        const int c = lane + i * 32;
        const float v = outtmp[(size_t)row * 256 + c] + x[(size_t)row * 256 + c];
        h[i] = v; sum += v; sq = fmaf(v, v, sq);
    }
#pragma unroll
    for (int o = 16; o; o >>= 1) {
        sum += __shfl_xor_sync(0xffffffffu, sum, o);
        sq  += __shfl_xor_sync(0xffffffffu, sq,  o);
    }
    const float mu  = sum * (1.f / 256.f);
    const float var = sq * (1.f / 256.f) - mu * mu;
    const float inv = rsqrtf(var + 1e-5f);
#pragma unroll
    for (int i = 0; i < 8; i++) {
        const int c = lane + i * 32;
        out[(size_t)row * 256 + c] = (h[i] - mu) * inv * g[c] + beta[c];
    }
}

// ---------------------------------------------------------------------------
extern "C" void kernel_launch(void* const* d_in, const int* in_sizes, int n_in,
                              void* d_out, int out_size)
{
    const float* x       = (const float*)d_in[0];
    const float* in_w    = (const float*)d_in[1];
    const float* conv_w  = (const float*)d_in[2];
    const float* conv_b  = (const float*)d_in[3];
    const float* xproj_w = (const float*)d_in[4];
    const float* dt_w    = (const float*)d_in[5];
    const float* dt_b    = (const float*)d_in[6];
    const float* A_log   = (const float*)d_in[7];
    const float* Dw      = (const float*)d_in[8];
    const float* out_w   = (const float*)d_in[9];
    const float* ln_g    = (const float*)d_in[10];
    const float* ln_b    = (const float*)d_in[11];
    float* out = (float*)d_out;

    float* base = nullptr;
    cudaGetSymbolAddress((void**)&base, g_scratch);
    float* xz     = base + OFF_XZ;
    float* uc     = base + OFF_UC;
    float* uct    = base + OFF_UCT;
    float* xdbl   = base + OFF_XDBL;
    float* deltat = base + OFF_DELTAT;
    float* yscant = base + OFF_YSCANT;
    float* outtmp = base + OFF_OUTTMP;
    __nv_bfloat16* xh  = (__nv_bfloat16*)(base + OFF_XH);
    __nv_bfloat16* xl  = (__nv_bfloat16*)(base + OFF_XL);
    __nv_bfloat16* yh  = (__nv_bfloat16*)(base + OFF_YH);
    __nv_bfloat16* yl  = (__nv_bfloat16*)(base + OFF_YL);
    __nv_bfloat16* wih = (__nv_bfloat16*)(base + OFF_WIH);
    __nv_bfloat16* wil = (__nv_bfloat16*)(base + OFF_WIL);
    __nv_bfloat16* woh = (__nv_bfloat16*)(base + OFF_WOH);
    __nv_bfloat16* wol = (__nv_bfloat16*)(base + OFF_WOL);

    // 0. pre-split fp32 -> bf16 hi/lo: x, in_w, out_w
    split_kernel<<<(MROWS * DMODEL / 4 + 255) / 256, 256>>>(
        (const float4*)x, (uint2*)xh, (uint2*)xl, MROWS * DMODEL / 4);
    split_kernel<<<(1024 * DMODEL / 4 + 255) / 256, 256>>>(
        (const float4*)in_w, (uint2*)wih, (uint2*)wil, 1024 * DMODEL / 4);
    split_kernel<<<(DMODEL * DINNER / 4 + 255) / 256, 256>>>(
        (const float4*)out_w, (uint2*)woh, (uint2*)wol, DMODEL * DINNER / 4);

    // 1. in_proj: xz = x @ in_w^T   (M=32768, N=1024, K=256) [tensor cores]
    gemm_tc2_kernel<<<dim3(1024 / 128, MROWS / 128), 256>>>(
        xh, xl, wih, wil, xz, MROWS, 1024, DMODEL);

    // 2. conv4 + SiLU (+ transpose)
    conv_silu_kernel<<<dim3(DINNER / 32, SEQLEN / 32, BATCH), 256>>>(xz, conv_w, conv_b, uc, uct);

    // 3. x_proj: xdbl = uc @ xproj_w^T   (N=48, K=512)
    sgemm_kernel<<<dim3(1, MROWS / 128), 256>>>(uc, xproj_w, xdbl, MROWS, 48, 512);

    // 4. dt_proj + softplus (transposed write)
    dtproj_kernel<<<dim3(DINNER / 32, MROWS / 32), 256>>>(xdbl, dt_w, dt_b, deltat);

    // 5. selective scan (4096 channels, 2 per warp -> 256 blocks)
    scan_kernel<<<NCH / 16, 256>>>(deltat, uct, xdbl, A_log, yscant);

    // 6. gate + skip (writes bf16 hi/lo splits of y)
    gate_kernel<<<dim3(DINNER / 32, SEQLEN / 32, BATCH), 256>>>(yscant, uc, xz, Dw, yh, yl);

    // 7. out_proj: outtmp = y @ out_w^T   (M=32768, N=256, K=512) [tensor cores]
    gemm_tc2_kernel<<<dim3(256 / 128, MROWS / 128), 256>>>(
        yh, yl, woh, wol, outtmp, MROWS, 256, DINNER);

    // 8. residual + LayerNorm
    ln_kernel<<<MROWS / 8, 256>>>(outtmp, x, ln_g, ln_b, out);
}

// round 9
// speedup vs baseline: 1.4969x; 1.0181x over previous
#include <cuda_runtime.h>
#include <cuda_bf16.h>
#include <math.h>
#include <stdint.h>

// ---------------------------------------------------------------------------
// MambaBottleneck: B=8, L=4096, D_MODEL=256, D_INNER=512, D_STATE=16,
// DT_RANK=16, D_CONV=4.  M = B*L = 32768 rows.
// ---------------------------------------------------------------------------

#define BATCH   8
#define SEQLEN  4096
#define DMODEL  256
#define DINNER  512
#define DSTATE  16
#define MROWS   (BATCH * SEQLEN)          // 32768
#define NCH     (BATCH * DINNER)          // 4096

// scratch layout (float units; bf16 arrays use half-sized float counts)
#define OFF_XZ      0
#define SZ_XZ       (MROWS * 1024)
#define OFF_UC      (OFF_XZ + SZ_XZ)
#define SZ_UC       (MROWS * DINNER)
#define OFF_UCT     (OFF_UC + SZ_UC)
#define SZ_UCT      (NCH * SEQLEN)
#define OFF_XDBL    (OFF_UCT + SZ_UCT)
#define SZ_XDBL     (MROWS * 48)
#define OFF_DELTAT  (OFF_XDBL + SZ_XDBL)
#define SZ_DELTAT   (NCH * SEQLEN)
#define OFF_YSCANT  (OFF_DELTAT + SZ_DELTAT)
#define SZ_YSCANT   (NCH * SEQLEN)
#define OFF_OUTTMP  (OFF_YSCANT + SZ_YSCANT)
#define SZ_OUTTMP   (MROWS * DMODEL)
#define OFF_XH      (OFF_OUTTMP + SZ_OUTTMP)
#define SZ_XH       (MROWS * DMODEL / 2)
#define OFF_XL      (OFF_XH + SZ_XH)
#define OFF_YH      (OFF_XL + SZ_XH)
#define SZ_YH       (MROWS * DINNER / 2)
#define OFF_YL      (OFF_YH + SZ_YH)
#define OFF_WIH     (OFF_YL + SZ_YH)
#define SZ_WIH      (1024 * DMODEL / 2)
#define OFF_WIL     (OFF_WIH + SZ_WIH)
#define OFF_WOH     (OFF_WIL + SZ_WIH)
#define SZ_WOH      (DMODEL * DINNER / 2)
#define OFF_WOL     (OFF_WOH + SZ_WOH)
#define SCRATCH_TOTAL (OFF_WOL + SZ_WOH)

static __device__ float g_scratch[SCRATCH_TOTAL];

// ---------------------------------------------------------------------------
// fp32 -> bf16 hi/lo split (vectorized float4 -> 2x uint2)
// ---------------------------------------------------------------------------
__global__ __launch_bounds__(256) void split_kernel(
    const float4* __restrict__ src, uint2* __restrict__ h,
    uint2* __restrict__ l, int n4)
{
    const int i = blockIdx.x * blockDim.x + threadIdx.x;
    if (i >= n4) return;
    const float4 v = src[i];
    __nv_bfloat162 h0, h1, l0, l1;
    h0.x = __float2bfloat16(v.x); h0.y = __float2bfloat16(v.y);
    h1.x = __float2bfloat16(v.z); h1.y = __float2bfloat16(v.w);
    l0.x = __float2bfloat16(v.x - __bfloat162float(h0.x));
    l0.y = __float2bfloat16(v.y - __bfloat162float(h0.y));
    l1.x = __float2bfloat16(v.z - __bfloat162float(h1.x));
    l1.y = __float2bfloat16(v.w - __bfloat162float(h1.y));
    h[i] = make_uint2(*(uint32_t*)&h0, *(uint32_t*)&h1);
    l[i] = make_uint2(*(uint32_t*)&l0, *(uint32_t*)&l1);
}

// ---------------------------------------------------------------------------
// Tensor-core GEMM, pre-split bf16, cp.async double-buffered, STATIC 48KB smem.
// C = A @ W^T, acc = Ah*Wh + Ah*Wl + Al*Wh. Block tile 128x128x16, 8 warps
// (4m x 2n), warp tile 32x64. Smem rows stride 12 words (conflict-free:
// g*12 mod 32 = {0,12,24,4,16,28,8,20}). __launch_bounds__(256,2).
// ---------------------------------------------------------------------------
__device__ __forceinline__ void mma_bf16(float* c, const uint32_t* a,
                                         uint32_t b0, uint32_t b1)
{
    asm volatile(
        "mma.sync.aligned.m16n8k16.row.col.f32.bf16.bf16.f32 "
        "{%0,%1,%2,%3}, {%4,%5,%6,%7}, {%8,%9}, {%0,%1,%2,%3};"
        : "+f"(c[0]), "+f"(c[1]), "+f"(c[2]), "+f"(c[3])
        : "r"(a[0]), "r"(a[1]), "r"(a[2]), "r"(a[3]), "r"(b0), "r"(b1));
}

__device__ __forceinline__ void cp16(uint32_t smem_addr, const void* gptr)
{
    asm volatile("cp.async.ca.shared.global [%0], [%1], 16;"
                 :: "r"(smem_addr), "l"(gptr));
}

#define SPAD 12   // 8 data words (16 bf16) + 4 pad

__global__ __launch_bounds__(256, 2) void gemm_tc4_kernel(
    const __nv_bfloat16* __restrict__ Ah_, const __nv_bfloat16* __restrict__ Al_,
    const __nv_bfloat16* __restrict__ Wh_, const __nv_bfloat16* __restrict__ Wl_,
    float* __restrict__ C, int M, int N, int K)
{
    __shared__ uint32_t smem[2][4][128][SPAD];   // 49152 bytes (static)

    const int bm = blockIdx.y * 128;
    const int bn = blockIdx.x * 128;
    const int tid = threadIdx.x;
    const int lane = tid & 31;
    const int g   = lane >> 2;     // 0..7
    const int tig = lane & 3;      // 0..3
    const int w   = tid >> 5;
    const int wm  = (w >> 1) * 32; // 4 warps along m
    const int wn  = (w & 1) * 64;  // 2 warps along n

    // copy assignment: thread t -> row = t>>1, 16B chunk = (t&1)
    const int crow  = tid >> 1;          // 0..127
    const int chalf = tid & 1;           // 0 or 1
    const int ccol  = chalf * 8;         // bf16 element offset
    const int cword = chalf * 4;         // smem word offset

    const __nv_bfloat16* gp[4];
    gp[0] = Ah_ + (size_t)(bm + crow) * K + ccol;
    gp[1] = Al_ + (size_t)(bm + crow) * K + ccol;
    gp[2] = Wh_ + (size_t)(bn + crow) * K + ccol;
    gp[3] = Wl_ + (size_t)(bn + crow) * K + ccol;

    uint32_t sdst[4];
#pragma unroll
    for (int a = 0; a < 4; a++)
        sdst[a] = (uint32_t)__cvta_generic_to_shared(&smem[0][a][crow][cword]);
    const uint32_t stStride = 4 * 128 * SPAD * 4;   // bytes per stage

    float acc[2][8][4];
#pragma unroll
    for (int i = 0; i < 2; i++)
#pragma unroll
        for (int j = 0; j < 8; j++)
#pragma unroll
            for (int q = 0; q < 4; q++) acc[i][j][q] = 0.f;

    const int KT = K >> 4;   // k-tiles of 16

    // issue k-tile kt into stage st
    auto issue = [&](int kt, int st) {
        const int o = kt * 16;
        const uint32_t sb = (uint32_t)st * stStride;
#pragma unroll
        for (int a = 0; a < 4; a++)
            cp16(sdst[a] + sb, gp[a] + o);
    };

    issue(0, 0);
    asm volatile("cp.async.commit_group;");

    for (int kt = 0; kt < KT; kt++) {
        const int st = kt & 1;
        if (kt + 1 < KT) {
            issue(kt + 1, st ^ 1);
            asm volatile("cp.async.commit_group;");
            asm volatile("cp.async.wait_group 1;");
        } else {
            asm volatile("cp.async.wait_group 0;");
        }
        __syncthreads();

        // fragment loads + mma (one k16 step)
        uint32_t ah[2][4], al[2][4];
#pragma unroll
        for (int im = 0; im < 2; im++) {
            const int r = wm + im * 16 + g;
            ah[im][0] = smem[st][0][r][tig];         al[im][0] = smem[st][1][r][tig];
            ah[im][1] = smem[st][0][r + 8][tig];     al[im][1] = smem[st][1][r + 8][tig];
            ah[im][2] = smem[st][0][r][tig + 4];     al[im][2] = smem[st][1][r][tig + 4];
            ah[im][3] = smem[st][0][r + 8][tig + 4]; al[im][3] = smem[st][1][r + 8][tig + 4];
        }
#pragma unroll
        for (int jn = 0; jn < 8; jn++) {
            const int nr = wn + jn * 8 + g;
            const uint32_t bh0 = smem[st][2][nr][tig], bh1 = smem[st][2][nr][tig + 4];
            const uint32_t bl0 = smem[st][3][nr][tig], bl1 = smem[st][3][nr][tig + 4];
#pragma unroll
            for (int im = 0; im < 2; im++) {
                mma_bf16(acc[im][jn], ah[im], bh0, bh1);  // hi*hi
                mma_bf16(acc[im][jn], ah[im], bl0, bl1);  // hi*lo
                mma_bf16(acc[im][jn], al[im], bh0, bh1);  // lo*hi
            }
        }
        __syncthreads();
    }

#pragma unroll
    for (int im = 0; im < 2; im++) {
        const int row = bm + wm + im * 16 + g;
#pragma unroll
        for (int jn = 0; jn < 8; jn++) {
            const int col = bn + wn + jn * 8 + 2 * tig;
            float2 v0 = make_float2(acc[im][jn][0], acc[im][jn][1]);
            float2 v1 = make_float2(acc[im][jn][2], acc[im][jn][3]);
            *(float2*)(C + (size_t)row * N + col)       = v0;
            *(float2*)(C + (size_t)(row + 8) * N + col) = v1;
        }
    }
}

// ---------------------------------------------------------------------------
// SGEMM 128x64x16 (for x_proj, N=48 with guard).
// ---------------------------------------------------------------------------
__global__ __launch_bounds__(256) void sgemm_kernel(
    const float* __restrict__ A, const float* __restrict__ W,
    float* __restrict__ C, int M, int N, int K)
{
    __shared__ float As[16 * 128];
    __shared__ float Bs[16 * 64];

    const int bm = blockIdx.y * 128;
    const int bn = blockIdx.x * 64;
    const int tid = threadIdx.x;
    const int tx = tid & 15;
    const int ty = tid >> 4;

    float acc[8][4];
#pragma unroll
    for (int i = 0; i < 8; i++)
#pragma unroll
        for (int j = 0; j < 4; j++) acc[i][j] = 0.f;

    const int ar = tid >> 1, ak = (tid & 1) * 8;
    const int br = tid >> 2, bk = (tid & 3) * 4;
    const bool bval = (bn + br) < N;

    const float* Ap = A + (size_t)(bm + ar) * K + ak;
    const float* Wp = W + (size_t)(bval ? (bn + br) : 0) * K + bk;

    for (int k0 = 0; k0 < K; k0 += 16) {
        float4 a0 = *(const float4*)(Ap + k0);
        float4 a1 = *(const float4*)(Ap + k0 + 4);
        float4 bv = *(const float4*)(Wp + k0);
        if (!bval) { bv.x = bv.y = bv.z = bv.w = 0.f; }

        As[(ak + 0) * 128 + ar] = a0.x;
        As[(ak + 1) * 128 + ar] = a0.y;
        As[(ak + 2) * 128 + ar] = a0.z;
        As[(ak + 3) * 128 + ar] = a0.w;
        As[(ak + 4) * 128 + ar] = a1.x;
        As[(ak + 5) * 128 + ar] = a1.y;
        As[(ak + 6) * 128 + ar] = a1.z;
        As[(ak + 7) * 128 + ar] = a1.w;
        Bs[(bk + 0) * 64 + br] = bv.x;
        Bs[(bk + 1) * 64 + br] = bv.y;
        Bs[(bk + 2) * 64 + br] = bv.z;
        Bs[(bk + 3) * 64 + br] = bv.w;
        __syncthreads();

#pragma unroll
        for (int kk = 0; kk < 16; kk++) {
            float4 av0 = *(const float4*)&As[kk * 128 + ty * 8];
            float4 av1 = *(const float4*)&As[kk * 128 + ty * 8 + 4];
            float4 bv4 = *(const float4*)&Bs[kk * 64 + tx * 4];
            float a[8] = {av0.x, av0.y, av0.z, av0.w, av1.x, av1.y, av1.z, av1.w};
            float b[4] = {bv4.x, bv4.y, bv4.z, bv4.w};
#pragma unroll
            for (int i = 0; i < 8; i++)
#pragma unroll
                for (int j = 0; j < 4; j++)
                    acc[i][j] = fmaf(a[i], b[j], acc[i][j]);
        }
        __syncthreads();
    }

#pragma unroll
    for (int i = 0; i < 8; i++) {
        const int row = bm + ty * 8 + i;
#pragma unroll
        for (int j = 0; j < 4; j++) {
            const int col = bn + tx * 4 + j;
            if (col < N) C[(size_t)row * N + col] = acc[i][j];
        }
    }
}

// ---------------------------------------------------------------------------
// Depthwise causal conv4 + SiLU. Writes uc (M,512) and uct (CH,L).
// ---------------------------------------------------------------------------
__global__ __launch_bounds__(256) void conv_silu_kernel(
    const float* __restrict__ xz, const float* __restrict__ cw,
    const float* __restrict__ cb, float* __restrict__ uc,
    float* __restrict__ uct)
{
    __shared__ float su[35][33];
    __shared__ float so[32][33];
    const int d0 = blockIdx.x * 32;
    const int l0 = blockIdx.y * 32;
    const int b  = blockIdx.z;
    const int tx = threadIdx.x & 31;
    const int ty = threadIdx.x >> 5;

    for (int r = ty; r < 35; r += 8) {
        const int l = l0 - 3 + r;
        float v = 0.f;
        if (l >= 0) v = xz[(size_t)(b * SEQLEN + l) * 1024 + d0 + tx];
        su[r][tx] = v;
    }
    __syncthreads();

    const int d = d0 + tx;
    const float w0 = cw[d * 4 + 0], w1 = cw[d * 4 + 1];
    const float w2 = cw[d * 4 + 2], w3 = cw[d * 4 + 3];
    const float bb = cb[d];

    for (int ll = ty; ll < 32; ll += 8) {
        float acc = su[ll][tx] * w0 + su[ll + 1][tx] * w1
                  + su[ll + 2][tx] * w2 + su[ll + 3][tx] * w3 + bb;
        const float sv = acc / (1.f + __expf(-acc));
        const int m = b * SEQLEN + l0 + ll;
        uc[(size_t)m * DINNER + d] = sv;
        so[ll][tx] = sv;
    }
    __syncthreads();

    for (int dd = ty; dd < 32; dd += 8)
        uct[(size_t)(b * DINNER + d0 + dd) * SEQLEN + l0 + tx] = so[tx][dd];
}

// ---------------------------------------------------------------------------
// delta_t(CH,L) = softplus(xdbl[:, 0:16] @ dt_proj_w^T + dt_proj_b)
// ---------------------------------------------------------------------------
__global__ __launch_bounds__(256) void dtproj_kernel(
    const float* __restrict__ xdbl, const float* __restrict__ dtw,
    const float* __restrict__ dtb, float* __restrict__ deltat)
{
    __shared__ float sdt[32][17];
    __shared__ float sw[32][17];
    __shared__ float so[32][33];
    const int d0 = blockIdx.x * 32;
    const int m0 = blockIdx.y * 32;
    const int tid = threadIdx.x;

    {
        const int r = tid >> 4, c = tid & 15;
        sdt[r][c]      = xdbl[(size_t)(m0 + r) * 48 + c];
        sdt[r + 16][c] = xdbl[(size_t)(m0 + r + 16) * 48 + c];
        sw[r][c]       = dtw[(d0 + r) * 16 + c];
        sw[r + 16][c]  = dtw[(d0 + r + 16) * 16 + c];
    }
    __syncthreads();

    const int dloc = tid & 31;
    const float bias = dtb[d0 + dloc];
    for (int ll = tid >> 5; ll < 32; ll += 8) {
        float acc = bias;
#pragma unroll
        for (int k = 0; k < 16; k++) acc = fmaf(sdt[ll][k], sw[dloc][k], acc);
        so[ll][dloc] = fmaxf(acc, 0.f) + __logf(1.f + __expf(-fabsf(acc)));
    }
    __syncthreads();

    const int b  = m0 / SEQLEN;
    const int l0 = m0 % SEQLEN;
    for (int dd = tid >> 5; dd < 32; dd += 8)
        deltat[(size_t)(b * DINNER + d0 + dd) * SEQLEN + l0 + dloc] = so[dloc][dd];
}

// ---------------------------------------------------------------------------
// Selective scan. Half-warp (16 lanes) per channel, lane = state index s.
// ---------------------------------------------------------------------------
__global__ __launch_bounds__(256) void scan_kernel(
    const float* __restrict__ deltat, const float* __restrict__ uct,
    const float* __restrict__ xdbl, const float* __restrict__ Alog,
    float* __restrict__ yscant)
{
    const int warp = (blockIdx.x * blockDim.x + threadIdx.x) >> 5;
    const int lane = threadIdx.x & 31;
    const int half = lane >> 4;
    const int s    = lane & 15;
    const int ch   = warp * 2 + half;      // 0..4095
    const int b    = ch >> 9;
    const int d    = ch & 511;

    const float A = -__expf(Alog[d * DSTATE + s]);
    float state = 0.f;

    const float4* dptr4 = (const float4*)(deltat + (size_t)ch * SEQLEN);
    const float4* uptr4 = (const float4*)(uct    + (size_t)ch * SEQLEN);
    const float* xB   = xdbl + (size_t)b * SEQLEN * 48 + 16 + s;
    float* yout = yscant + (size_t)ch * SEQLEN;

    for (int l4 = 0; l4 < SEQLEN / 4; l4++) {
        const float4 dt4 = __ldg(dptr4 + l4);
        const float4 ut4 = __ldg(uptr4 + l4);
        const float dts[4] = {dt4.x, dt4.y, dt4.z, dt4.w};
        const float uts[4] = {ut4.x, ut4.y, ut4.z, ut4.w};
#pragma unroll
        for (int j = 0; j < 4; j++) {
            const float Bv = __ldg(xB);
            const float Cv = __ldg(xB + 16);
            xB += 48;
            const float dA = __expf(dts[j] * A);
            state = fmaf(state, dA, dts[j] * uts[j] * Bv);
            float p = state * Cv;
            p += __shfl_xor_sync(0xffffffffu, p, 8);
            p += __shfl_xor_sync(0xffffffffu, p, 4);
            p += __shfl_xor_sync(0xffffffffu, p, 2);
            p += __shfl_xor_sync(0xffffffffu, p, 1);
            if (s == 0) yout[l4 * 4 + j] = p;
        }
    }
}

// ---------------------------------------------------------------------------
// Gate: y = (yscan^T + D*uc) * silu(z), written as bf16 hi/lo splits.
// ---------------------------------------------------------------------------
__global__ __launch_bounds__(256) void gate_kernel(
    const float* __restrict__ yscant, const float* __restrict__ uc,
    const float* __restrict__ xz, const float* __restrict__ Dw,
    __nv_bfloat16* __restrict__ yh, __nv_bfloat16* __restrict__ yl)
{
    __shared__ float s[32][33];
    const int d0 = blockIdx.x * 32;
    const int l0 = blockIdx.y * 32;
    const int b  = blockIdx.z;
    const int tx = threadIdx.x & 31;
    const int ty = threadIdx.x >> 5;

    for (int dd = ty; dd < 32; dd += 8)
        s[dd][tx] = yscant[(size_t)(b * DINNER + d0 + dd) * SEQLEN + l0 + tx];
    __syncthreads();

    const int d = d0 + tx;
    const float Dv = Dw[d];
    for (int ll = ty; ll < 32; ll += 8) {
        const int m = b * SEQLEN + l0 + ll;
        const float ucv = uc[(size_t)m * DINNER + d];
        const float zv  = xz[(size_t)m * 1024 + DINNER + d];
        const float silu_z = zv / (1.f + __expf(-zv));
        const float v = (s[tx][ll] + Dv * ucv) * silu_z;
        const __nv_bfloat16 hv = __float2bfloat16(v);
        yh[(size_t)m * DINNER + d] = hv;
        yl[(size_t)m * DINNER + d] = __float2bfloat16(v - __bfloat162float(hv));
    }
}

// ---------------------------------------------------------------------------
// Residual + LayerNorm. Warp per row.
// ---------------------------------------------------------------------------
__global__ __launch_bounds__(256) void ln_kernel(
    const float* __restrict__ outtmp, const float* __restrict__ x,
    const float* __restrict__ g, const float* __restrict__ beta,
    float* __restrict__ out)
{
    const int warp = threadIdx.x >> 5;
    const int lane = threadIdx.x & 31;
    const int row = blockIdx.x * 8 + warp;

    float h[8];
    float sum = 0.f, sq = 0.f;
#pragma unroll
    for (int i = 0; i < 8; i++) {
        const int c = lane + i * 32;
        const float v = outtmp[(size_t)row * 256 + c] + x[(size_t)row * 256 + c];
        h[i] = v; sum += v; sq = fmaf(v, v, sq);
    }
#pragma unroll
    for (int o = 16; o; o >>= 1) {
        sum += __shfl_xor_sync(0xffffffffu, sum, o);
        sq  += __shfl_xor_sync(0xffffffffu, sq,  o);
    }
    const float mu  = sum * (1.f / 256.f);
    const float var = sq * (1.f / 256.f) - mu * mu;
    const float inv = rsqrtf(var + 1e-5f);
#pragma unroll
    for (int i = 0; i < 8; i++) {
        const int c = lane + i * 32;
        out[(size_t)row * 256 + c] = (h[i] - mu) * inv * g[c] + beta[c];
    }
}

// ---------------------------------------------------------------------------
extern "C" void kernel_launch(void* const* d_in, const int* in_sizes, int n_in,
                              void* d_out, int out_size)
{
    const float* x       = (const float*)d_in[0];
    const float* in_w    = (const float*)d_in[1];
    const float* conv_w  = (const float*)d_in[2];
    const float* conv_b  = (const float*)d_in[3];
    const float* xproj_w = (const float*)d_in[4];
    const float* dt_w    = (const float*)d_in[5];
    const float* dt_b    = (const float*)d_in[6];
    const float* A_log   = (const float*)d_in[7];
    const float* Dw      = (const float*)d_in[8];
    const float* out_w   = (const float*)d_in[9];
    const float* ln_g    = (const float*)d_in[10];
    const float* ln_b    = (const float*)d_in[11];
    float* out = (float*)d_out;

    float* base = nullptr;
    cudaGetSymbolAddress((void**)&base, g_scratch);
    float* xz     = base + OFF_XZ;
    float* uc     = base + OFF_UC;
    float* uct    = base + OFF_UCT;
    float* xdbl   = base + OFF_XDBL;
    float* deltat = base + OFF_DELTAT;
    float* yscant = base + OFF_YSCANT;
    float* outtmp = base + OFF_OUTTMP;
    __nv_bfloat16* xh  = (__nv_bfloat16*)(base + OFF_XH);
    __nv_bfloat16* xl  = (__nv_bfloat16*)(base + OFF_XL);
    __nv_bfloat16* yh  = (__nv_bfloat16*)(base + OFF_YH);
    __nv_bfloat16* yl  = (__nv_bfloat16*)(base + OFF_YL);
    __nv_bfloat16* wih = (__nv_bfloat16*)(base + OFF_WIH);
    __nv_bfloat16* wil = (__nv_bfloat16*)(base + OFF_WIL);
    __nv_bfloat16* woh = (__nv_bfloat16*)(base + OFF_WOH);
    __nv_bfloat16* wol = (__nv_bfloat16*)(base + OFF_WOL);

    // 0. pre-split fp32 -> bf16 hi/lo: x, in_w, out_w
    split_kernel<<<(MROWS * DMODEL / 4 + 255) / 256, 256>>>(
        (const float4*)x, (uint2*)xh, (uint2*)xl, MROWS * DMODEL / 4);
    split_kernel<<<(1024 * DMODEL / 4 + 255) / 256, 256>>>(
        (const float4*)in_w, (uint2*)wih, (uint2*)wil, 1024 * DMODEL / 4);
    split_kernel<<<(DMODEL * DINNER / 4 + 255) / 256, 256>>>(
        (const float4*)out_w, (uint2*)woh, (uint2*)wol, DMODEL * DINNER / 4);

    // 1. in_proj: xz = x @ in_w^T   (M=32768, N=1024, K=256) [tensor cores]
    gemm_tc4_kernel<<<dim3(1024 / 128, MROWS / 128), 256>>>(
        xh, xl, wih, wil, xz, MROWS, 1024, DMODEL);

    // 2. conv4 + SiLU (+ transpose)
    conv_silu_kernel<<<dim3(DINNER / 32, SEQLEN / 32, BATCH), 256>>>(xz, conv_w, conv_b, uc, uct);

    // 3. x_proj: xdbl = uc @ xproj_w^T   (N=48, K=512)
    sgemm_kernel<<<dim3(1, MROWS / 128), 256>>>(uc, xproj_w, xdbl, MROWS, 48, 512);

    // 4. dt_proj + softplus (transposed write)
    dtproj_kernel<<<dim3(DINNER / 32, MROWS / 32), 256>>>(xdbl, dt_w, dt_b, deltat);

    // 5. selective scan (4096 channels, 2 per warp -> 256 blocks)
    scan_kernel<<<NCH / 16, 256>>>(deltat, uct, xdbl, A_log, yscant);

    // 6. gate + skip (writes bf16 hi/lo splits of y)
    gate_kernel<<<dim3(DINNER / 32, SEQLEN / 32, BATCH), 256>>>(yscant, uc, xz, Dw, yh, yl);

    // 7. out_proj: outtmp = y @ out_w^T   (M=32768, N=256, K=512) [tensor cores]
    gemm_tc4_kernel<<<dim3(256 / 128, MROWS / 128), 256>>>(
        yh, yl, woh, wol, outtmp, MROWS, 256, DINNER);

    // 8. residual + LayerNorm
    ln_kernel<<<MROWS / 8, 256>>>(outtmp, x, ln_g, ln_b, out);
}